// round 14
// baseline (speedup 1.0000x reference)
#include <cuda_runtime.h>
#include <cuda_fp16.h>
#include <cstdint>

#define N_NODES 20000
#define N_EDGES 320000
#define E_TOT   (N_EDGES + N_NODES)   /* 340000, with self loops */
#define D_IN  32
#define D     128
#define DV    16
#define NV    8
#define D_OUT 8

#define LO_SCALE   2048.0f
#define LO_INV     4.8828125e-4f   /* 1/2048 */

// ---------------- scratch (static device memory; no allocs allowed) ----------
// activations packed per element: uint32 = {fp16 hi (low 16), fp16 lo*2048 (high 16)}
__device__ uint32_t g_hS0[N_NODES * D];
__device__ uint32_t g_hS1[N_NODES * D];
__device__ __half   g_Th [N_NODES * D];
__device__ __half   g_Sh [N_NODES * D];
__device__ __half   g_Hnh[N_NODES * D];     // PERMUTED: element (h,dv) at dv*8+h
__device__ __half   g_lgh[E_TOT * NV];      // per-edge per-head logits (fp16)
__device__ float    g_s  [N_NODES * NV];
__device__ float    g_agg[N_NODES * DV];
__device__ int      g_is64;
// packed weights, TRANSPOSED to [n][k] so B chunks are k-contiguous
__device__ uint32_t g_W1p [D * D_IN];       // [128][32]
__device__ uint32_t g_W2p [D * D];          // [128][128]
__device__ uint32_t g_Wfat[2][384 * D];     // [Wt|Ws|Wh rows][128]
__device__ uint32_t g_Wop [2][D * DV];      // [128][16]
__device__ float    g_bfat[2][384];

// ---------------- dtype detection for edge_index ----------------------------
__global__ void detect_kernel(const int* __restrict__ idx) {
    int tid = threadIdx.x;
    int z = (idx[2 * tid + 1] == 0) ? 1 : 0;
    int all = __syncthreads_and(z);
    if (tid == 0) g_is64 = all;
}

__device__ __forceinline__ void load_edge(const void* __restrict__ idx, int e,
                                          int& s, int& d) {
    if (e >= N_EDGES) { s = d = e - N_EDGES; return; }  // self loop
    if (g_is64) {
        const long long* p = (const long long*)idx;
        s = (int)p[e];
        d = (int)p[N_EDGES + e];
    } else {
        const int* p = (const int*)idx;
        s = p[e];
        d = p[N_EDGES + e];
    }
}

// ---------------- fp16 hi/lo split helpers -----------------------------------
// lo plane scaled by 2^11 so it stays in the fp16 NORMAL range.
__device__ __forceinline__ uint32_t packhl(float v) {
    __half h = __float2half_rn(v);
    __half l = __float2half_rn((v - __half2float(h)) * LO_SCALE);
    return (uint32_t)__half_as_ushort(h) | ((uint32_t)__half_as_ushort(l) << 16);
}

#define MMA_F16(d, a, b)                                                      \
    asm volatile("mma.sync.aligned.m16n8k16.row.col.f32.f16.f16.f32 "         \
                 "{%0,%1,%2,%3}, {%4,%5,%6,%7}, {%8,%9}, {%0,%1,%2,%3};"      \
                 : "+f"(d[0]), "+f"(d[1]), "+f"(d[2]), "+f"(d[3])             \
                 : "r"(a[0]), "r"(a[1]), "r"(a[2]), "r"(a[3]),                \
                   "r"(b[0]), "r"(b[1]))

__device__ __forceinline__ void cp16(uint32_t smem_addr, const void* gptr, int src_bytes) {
    asm volatile("cp.async.cg.shared.global [%0], [%1], 16, %2;"
                 :: "r"(smem_addr), "l"(gptr), "r"(src_bytes));
}
#define CP_COMMIT() asm volatile("cp.async.commit_group;" ::: "memory")
#define CP_WAIT1()  asm volatile("cp.async.wait_group 1;" ::: "memory")
#define CP_WAIT0()  asm volatile("cp.async.wait_group 0;" ::: "memory")

#define GEMM_SA 24
#define GEMM_SB 24
#define GEMM_SMEM_WORDS (3 * 64 * GEMM_SA + 3 * 128 * GEMM_SB)
#define GEMM_SMEM_BYTES (GEMM_SMEM_WORDS * 4)   /* 55296 */

// ---------------- fp16-split tensor GEMM, 3-stage cp.async -------------------
// C[M, 128 per y-block] = relu(A[M,K] @ W[K,N] + b).
// smem keeps PACKED {hi,lo} words; fragments = LDS.64 + 2x byte_perm in loop.
// 3-stage ring: tile i lives in buffer i%3. prefetch(t+2) targets buffer
// (t-1)%3 whose readers all passed the end-of-(t-1) barrier -> ONE barrier
// per tile, no race. wait_group 1 at iter t drains through tile t+1.
// BM=64, BN=128, BK=16; 8 warps, warp tile 16x64; dual accumulator epilogue.
template <int K, int MODE, bool FAT, bool AF32>
__global__ __launch_bounds__(256, 2) void
gemm_f16(const void* __restrict__ Av, const uint32_t* __restrict__ Wp,
         const float* __restrict__ bias,
         void* __restrict__ out0, void* __restrict__ out1, void* __restrict__ out2,
         int M) {
    constexpr int BK = 16;
    constexpr int T  = K / BK;

    extern __shared__ __align__(16) uint32_t smem_raw[];
    typedef uint32_t ABuf[64][GEMM_SA];
    typedef uint32_t BBuf[128][GEMM_SB];
    ABuf* As = reinterpret_cast<ABuf*>(smem_raw);                        // [3]
    BBuf* Bs = reinterpret_cast<BBuf*>(smem_raw + 3 * 64 * GEMM_SA);     // [3]

    const int tid  = threadIdx.x;
    const int lane = tid & 31;
    const int wid  = tid >> 5;
    const int wm   = wid & 3;    // rows wm*16 .. +15
    const int wn   = wid >> 2;   // cols wn*64 .. +63
    const int m0   = blockIdx.x * 64;
    const int y    = FAT ? blockIdx.y : 0;

    const uint32_t* Wy = Wp + (size_t)y * 128 * K;
    const float*    by = bias + y * 128;

    float acc[8][4], accL[8][4];
#pragma unroll
    for (int nt = 0; nt < 8; nt++)
#pragma unroll
        for (int j = 0; j < 4; j++) { acc[nt][j] = 0.f; accL[nt][j] = 0.f; }

    const int arow = tid >> 2;          // 0..63
    const int ak4  = (tid & 3) * 4;     // 0,4,8,12

    auto prefetch = [&](int t, int buf) {
        if (!AF32) {
            const uint32_t* Ap = (const uint32_t*)Av;
            uint32_t dst = (uint32_t)__cvta_generic_to_shared(&As[buf][arow][ak4]);
            cp16(dst, &Ap[(size_t)(m0 + arow) * K + t * BK + ak4],
                 (m0 + arow < M) ? 16 : 0);
        }
#pragma unroll
        for (int i = 0; i < 2; i++) {
            int idx = tid + i * 256;
            int n   = idx >> 2;          // 0..127
            int k4  = (idx & 3) * 4;
            uint32_t dst = (uint32_t)__cvta_generic_to_shared(&Bs[buf][n][k4]);
            cp16(dst, &Wy[(size_t)n * K + t * BK + k4], 16);
        }
    };

    auto stageA_f32 = [&](int t, int buf) {   // AF32 path: ldg + split + STS
        const float* Af = (const float*)Av;
        float4 aF = make_float4(0.f, 0.f, 0.f, 0.f);
        if (m0 + arow < M)
            aF = *reinterpret_cast<const float4*>(&Af[(size_t)(m0 + arow) * K + t * BK + ak4]);
        As[buf][arow][ak4 + 0] = packhl(aF.x);
        As[buf][arow][ak4 + 1] = packhl(aF.y);
        As[buf][arow][ak4 + 2] = packhl(aF.z);
        As[buf][arow][ak4 + 3] = packhl(aF.w);
    };

    auto computeTile = [&](int buf) {
        const int r  = lane >> 2;   // 0..7
        const int c2 = (lane & 3) * 2;
        const int mb = wm * 16 + r;

        uint2 a0 = *reinterpret_cast<const uint2*>(&As[buf][mb][c2]);
        uint2 a1 = *reinterpret_cast<const uint2*>(&As[buf][mb + 8][c2]);
        uint2 a2 = *reinterpret_cast<const uint2*>(&As[buf][mb][c2 + 8]);
        uint2 a3 = *reinterpret_cast<const uint2*>(&As[buf][mb + 8][c2 + 8]);
        uint32_t ah[4], al[4];
        ah[0] = __byte_perm(a0.x, a0.y, 0x5410); al[0] = __byte_perm(a0.x, a0.y, 0x7632);
        ah[1] = __byte_perm(a1.x, a1.y, 0x5410); al[1] = __byte_perm(a1.x, a1.y, 0x7632);
        ah[2] = __byte_perm(a2.x, a2.y, 0x5410); al[2] = __byte_perm(a2.x, a2.y, 0x7632);
        ah[3] = __byte_perm(a3.x, a3.y, 0x5410); al[3] = __byte_perm(a3.x, a3.y, 0x7632);

#pragma unroll
        for (int nt = 0; nt < 8; nt++) {
            int nb = wn * 64 + nt * 8 + r;
            uint2 b0 = *reinterpret_cast<const uint2*>(&Bs[buf][nb][c2]);
            uint2 b1 = *reinterpret_cast<const uint2*>(&Bs[buf][nb][c2 + 8]);
            uint32_t bh[2], bl[2];
            bh[0] = __byte_perm(b0.x, b0.y, 0x5410); bl[0] = __byte_perm(b0.x, b0.y, 0x7632);
            bh[1] = __byte_perm(b1.x, b1.y, 0x5410); bl[1] = __byte_perm(b1.x, b1.y, 0x7632);
            MMA_F16(acc[nt],  ah, bh);
            MMA_F16(accL[nt], al, bh);
            MMA_F16(accL[nt], ah, bl);
        }
    };

    if (AF32) {
        // small-K path, non-pipelined (T <= 2)
#pragma unroll
        for (int t = 0; t < T; t++) {
            stageA_f32(t, 0);
            prefetch(t, 0);         // B only (AF32 skips A in prefetch)
            CP_COMMIT();
            CP_WAIT0();
            __syncthreads();
            computeTile(0);
            __syncthreads();
        }
    } else {
        prefetch(0, 0); CP_COMMIT();
        if (T > 1) { prefetch(1, 1); }
        CP_COMMIT();
        CP_WAIT1();
        __syncthreads();
#pragma unroll
        for (int t = 0; t < T; t++) {
            if (t + 2 < T) prefetch(t + 2, (t + 2) % 3);
            CP_COMMIT();
            computeTile(t % 3);
            CP_WAIT1();
            __syncthreads();
        }
    }

    // ---- epilogue (relu always): c0,c1 -> (row, col..col+1), c2,c3 -> row+8
    const int r   = lane >> 2;
    const int c2  = (lane & 3) * 2;
    const int row = m0 + wm * 16 + r;

    const int mode = FAT ? 1 : MODE;
    const bool permHalf = FAT && (y == 2);   // Hnh: permuted half layout
    void* outp = FAT ? (y == 0 ? out0 : (y == 1 ? out1 : out2)) : out0;

#pragma unroll
    for (int nt = 0; nt < 8; nt++) {
        int col = wn * 64 + nt * 8 + c2;
        float b0 = by[col], b1 = by[col + 1];
        float v0 = fmaxf(acc[nt][0] + accL[nt][0] * LO_INV + b0, 0.f);
        float v1 = fmaxf(acc[nt][1] + accL[nt][1] * LO_INV + b1, 0.f);
        float v2 = fmaxf(acc[nt][2] + accL[nt][2] * LO_INV + b0, 0.f);
        float v3 = fmaxf(acc[nt][3] + accL[nt][3] * LO_INV + b1, 0.f);
        if (permHalf) {
            // column c = h*16+dv  ->  permuted position dv*8+h
            __half* C = (__half*)outp;
            int p0 = (col & 15) * 8 + (col >> 4);
            int p1 = ((col + 1) & 15) * 8 + ((col + 1) >> 4);
            if (row < M) {
                C[(size_t)row * 128 + p0] = __float2half_rn(v0);
                C[(size_t)row * 128 + p1] = __float2half_rn(v1);
            }
            if (row + 8 < M) {
                C[(size_t)(row + 8) * 128 + p0] = __float2half_rn(v2);
                C[(size_t)(row + 8) * 128 + p1] = __float2half_rn(v3);
            }
        } else if (mode == 0) {
            float* C = (float*)outp;
            if (row < M)
                *reinterpret_cast<float2*>(&C[(size_t)row * 128 + col]) = make_float2(v0, v1);
            if (row + 8 < M)
                *reinterpret_cast<float2*>(&C[(size_t)(row + 8) * 128 + col]) = make_float2(v2, v3);
        } else if (mode == 1) {
            __half2* C = (__half2*)outp;
            if (row < M)     C[(size_t)row * 64 + (col >> 1)]       = __floats2half2_rn(v0, v1);
            if (row + 8 < M) C[(size_t)(row + 8) * 64 + (col >> 1)] = __floats2half2_rn(v2, v3);
        } else {
            uint32_t* C = (uint32_t*)outp;
            if (row < M)
                *reinterpret_cast<uint2*>(&C[(size_t)row * 128 + col]) =
                    make_uint2(packhl(v0), packhl(v1));
            if (row + 8 < M)
                *reinterpret_cast<uint2*>(&C[(size_t)(row + 8) * 128 + col]) =
                    make_uint2(packhl(v2), packhl(v3));
        }
    }
}

// ---------------- weight/bias packing (once per launch; cheap) ---------------
// Weights are packed AND transposed to [n][k].
__global__ void pack_all(const float* __restrict__ W1, const float* __restrict__ W2,
                         const float* __restrict__ Wt0, const float* __restrict__ Ws0,
                         const float* __restrict__ Wh0, const float* __restrict__ Wo0,
                         const float* __restrict__ bt0, const float* __restrict__ bs0,
                         const float* __restrict__ bh0,
                         const float* __restrict__ Wt1, const float* __restrict__ Ws1,
                         const float* __restrict__ Wh1, const float* __restrict__ Wo1,
                         const float* __restrict__ bt1, const float* __restrict__ bs1,
                         const float* __restrict__ bh1) {
    int i = blockIdx.x * blockDim.x + threadIdx.x;
    if (i < D_IN * D) {                       // W1 [32][128] -> [n*32 + k]
        int k = i >> 7, n = i & 127;
        g_W1p[n * D_IN + k] = packhl(W1[i]);
        return;
    }
    i -= D_IN * D;
    if (i < D * D) {                          // W2 [128][128] -> [n*128 + k]
        int k = i >> 7, n = i & 127;
        g_W2p[n * D + k] = packhl(W2[i]);
        return;
    }
    i -= D * D;
    if (i < 6 * D * D) {                      // fat: [which*128 + n][k]
        int m = i / (D * D), r = i % (D * D);
        int l = m / 3, which = m % 3;
        const float* src = (l == 0) ? (which == 0 ? Wt0 : which == 1 ? Ws0 : Wh0)
                                    : (which == 0 ? Wt1 : which == 1 ? Ws1 : Wh1);
        int k = r >> 7, c = r & 127;
        g_Wfat[l][(size_t)(which * 128 + c) * D + k] = packhl(src[r]);
        return;
    }
    i -= 6 * D * D;
    if (i < 2 * DV * D) {                     // Wo [16][128] -> [n*16 + k]
        int l = i / (DV * D), r = i % (DV * D);
        int k = r >> 7, n = r & 127;
        g_Wop[l][n * DV + k] = packhl((l == 0 ? Wo0 : Wo1)[r]);
        return;
    }
    i -= 2 * DV * D;
    if (i < 2 * 384) {
        int l = i / 384, r = i % 384;
        const float* b = (l == 0) ? (r < 128 ? bt0 : r < 256 ? bs0 : bh0)
                                  : (r < 128 ? bt1 : r < 256 ? bs1 : bh1);
        g_bfat[l][r] = b[r & 127];
    }
}
#define PACK_TOTAL (D_IN * D + D * D + 6 * D * D + 2 * DV * D + 2 * 384)

// ---------------- per-layer init: s = 0, agg = 0 -----------------------------
__global__ void init_kernel() {
    int i = blockIdx.x * blockDim.x + threadIdx.x;
    if (i < N_NODES * NV) g_s[i] = 0.f;
    if (i < N_NODES * DV) g_agg[i] = 0.f;
}

// ---------------- pass 1: logits + exp + segment sum (no max needed) ---------
// Logits tiny & >=0 (ReLU outputs of 0.02-scale projections): shift-free
// softmax is exact; fp16 stores perturb logits ~1e-7 absolute.
__global__ void edge_logits(const void* __restrict__ idx) {
    int gw   = (blockIdx.x * blockDim.x + threadIdx.x) >> 5;
    int lane = threadIdx.x & 31;
    int sub  = lane >> 4;
    int l    = lane & 15;
    int e    = gw * 2 + sub;
    bool ok  = (e < E_TOT);

    float v = 0.f;
    int s = 0, d = 0;
    if (ok) {
        load_edge(idx, e, s, d);
        uint4 tv = *reinterpret_cast<const uint4*>(&g_Th[(size_t)d * D + l * 8]);
        uint4 sv = *reinterpret_cast<const uint4*>(&g_Sh[(size_t)s * D + l * 8]);
        const __half2* tp = reinterpret_cast<const __half2*>(&tv);
        const __half2* sp = reinterpret_cast<const __half2*>(&sv);
#pragma unroll
        for (int j = 0; j < 4; j++) {
            float2 tf = __half22float2(tp[j]);
            float2 sf = __half22float2(sp[j]);
            v += tf.x * sf.x + tf.y * sf.y;
        }
    }
    v += __shfl_xor_sync(0xffffffffu, v, 1);
    if (ok && (l & 1) == 0) {
        int h = l >> 1;
        g_lgh[(size_t)e * NV + h] = __float2half(v);
        atomicAdd(&g_s[(size_t)d * NV + h], expf(v));
    }
}

// ---------------- pass 2: alpha-weighted head-mean message + segment sum -----
// Hnh is PERMUTED (dv*8+h): lane l=dv gathers all 8 heads with ONE LDG.128.
__global__ void edge_aggregate(const void* __restrict__ idx) {
    int gw   = (blockIdx.x * blockDim.x + threadIdx.x) >> 5;
    int lane = threadIdx.x & 31;
    int sub  = lane >> 4;
    int l    = lane & 15;
    int e    = gw * 2 + sub;
    bool ok  = (e < E_TOT);

    int s = 0, d = 0;
    if (ok) load_edge(idx, e, s, d);

    float a = 0.f;
    if (ok && l < 8) {
        float v = __half2float(g_lgh[(size_t)e * NV + l]);
        a = expf(v) / (g_s[(size_t)d * NV + l] + 1e-12f);
    }

    uint4 hv = make_uint4(0u, 0u, 0u, 0u);
    if (ok) hv = *reinterpret_cast<const uint4*>(&g_Hnh[(size_t)s * D + l * 8]);
    const __half2* hp = reinterpret_cast<const __half2*>(&hv);

    float acc = 0.f;
    int gbase = sub * 16;
#pragma unroll
    for (int j = 0; j < 4; j++) {
        float a0 = __shfl_sync(0xffffffffu, a, gbase + 2 * j);
        float a1 = __shfl_sync(0xffffffffu, a, gbase + 2 * j + 1);
        float2 f = __half22float2(hp[j]);
        acc += f.x * a0 + f.y * a1;
    }
    if (ok) atomicAdd(&g_agg[(size_t)d * DV + l], acc * 0.125f);
}

// ---------------- output head: out[M,8] = (hi+lo/2048)[M,128] @ Wout + bout --
__global__ void out_kernel(const uint32_t* __restrict__ h, const float* __restrict__ W,
                           const float* __restrict__ b, float* __restrict__ out) {
    __shared__ float hs[32][132];
    __shared__ float Wsm[128][8];
    int tid = threadIdx.x;  // 256
    int m0  = blockIdx.x * 32;

#pragma unroll
    for (int i = 0; i < 4; i++) {
        int f = tid + i * 256;
        Wsm[f >> 3][f & 7] = W[f];
    }
#pragma unroll
    for (int i = 0; i < 4; i++) {
        int f4  = tid + i * 256;        // 1024 uint4 (4 packed elems each)
        int row = f4 >> 5;
        int c4  = (f4 & 31) * 4;
        uint4 v = make_uint4(0u, 0u, 0u, 0u);
        if (m0 + row < N_NODES)
            v = *reinterpret_cast<const uint4*>(&h[(size_t)(m0 + row) * 128 + c4]);
        uint32_t w[4] = {v.x, v.y, v.z, v.w};
#pragma unroll
        for (int j = 0; j < 4; j++) {
            __half2 p = *reinterpret_cast<__half2*>(&w[j]);
            hs[row][c4 + j] = __half2float(p.x) + __half2float(p.y) * LO_INV;
        }
    }
    __syncthreads();

    int row = tid >> 3, col = tid & 7;
    float acc = b[col];
#pragma unroll 8
    for (int k = 0; k < 128; k++) acc += hs[row][k] * Wsm[k][col];
    if (m0 + row < N_NODES) out[(size_t)(m0 + row) * 8 + col] = acc;
}

// ---------------- launch ------------------------------------------------------
extern "C" void kernel_launch(void* const* d_in, const int* in_sizes, int n_in,
                              void* d_out, int out_size) {
    const float* x    = (const float*)d_in[0];
    const void*  ei   = d_in[1];
    const float* W1   = (const float*)d_in[2];
    const float* b1   = (const float*)d_in[3];
    const float* W2   = (const float*)d_in[4];
    const float* b2   = (const float*)d_in[5];
    const float* Wout = (const float*)d_in[6];
    const float* bout = (const float*)d_in[7];
    float* out = (float*)d_out;

    uint32_t *hS0, *hS1, *W1p, *W2p, *Wfat, *Wop;
    __half *Th, *Sh, *Hnh;
    float *agg, *bfat;
    cudaGetSymbolAddress((void**)&hS0, g_hS0);
    cudaGetSymbolAddress((void**)&hS1, g_hS1);
    cudaGetSymbolAddress((void**)&Th, g_Th);
    cudaGetSymbolAddress((void**)&Sh, g_Sh);
    cudaGetSymbolAddress((void**)&Hnh, g_Hnh);
    cudaGetSymbolAddress((void**)&agg, g_agg);
    cudaGetSymbolAddress((void**)&W1p, g_W1p);
    cudaGetSymbolAddress((void**)&W2p, g_W2p);
    cudaGetSymbolAddress((void**)&Wfat, g_Wfat);
    cudaGetSymbolAddress((void**)&Wop, g_Wop);
    cudaGetSymbolAddress((void**)&bfat, g_bfat);

    // opt-in >48KB dynamic smem for the 3-stage ring
    cudaFuncSetAttribute(gemm_f16<32, 2, false, true>,
                         cudaFuncAttributeMaxDynamicSharedMemorySize, GEMM_SMEM_BYTES);
    cudaFuncSetAttribute(gemm_f16<128, 2, false, false>,
                         cudaFuncAttributeMaxDynamicSharedMemorySize, GEMM_SMEM_BYTES);
    cudaFuncSetAttribute(gemm_f16<128, 0, true, false>,
                         cudaFuncAttributeMaxDynamicSharedMemorySize, GEMM_SMEM_BYTES);
    cudaFuncSetAttribute(gemm_f16<16, 2, false, true>,
                         cudaFuncAttributeMaxDynamicSharedMemorySize, GEMM_SMEM_BYTES);

    const int GEMM_BLOCKS = (N_NODES + 63) / 64;        // 313
    const int EDGE_BLOCKS = (E_TOT * 16 + 255) / 256;   // 21250
    const int INIT_BLOCKS = (N_NODES * DV + 255) / 256; // 1250

    detect_kernel<<<1, 256>>>((const int*)ei);
    pack_all<<<(PACK_TOTAL + 255) / 256, 256>>>(
        W1, W2,
        (const float*)d_in[8],  (const float*)d_in[10], (const float*)d_in[12], (const float*)d_in[14],
        (const float*)d_in[9],  (const float*)d_in[11], (const float*)d_in[13],
        (const float*)d_in[16], (const float*)d_in[18], (const float*)d_in[20], (const float*)d_in[22],
        (const float*)d_in[17], (const float*)d_in[19], (const float*)d_in[21]);

    // embedding MLP (fp32 x in, packed activations out)
    gemm_f16<32, 2, false, true><<<GEMM_BLOCKS, 256, GEMM_SMEM_BYTES>>>(
        x, W1p, b1, hS0, nullptr, nullptr, N_NODES);
    gemm_f16<128, 2, false, false><<<GEMM_BLOCKS, 256, GEMM_SMEM_BYTES>>>(
        hS0, W2p, b2, hS1, nullptr, nullptr, N_NODES);

    uint32_t* hcur  = hS1;
    uint32_t* hnext = hS0;
    for (int l = 0; l < 2; l++) {
        const float* bo = (const float*)d_in[8 + l * 8 + 7];

        dim3 fatGrid(GEMM_BLOCKS, 3);
        gemm_f16<128, 0, true, false><<<fatGrid, 256, GEMM_SMEM_BYTES>>>(
            hcur, Wfat + (size_t)l * 384 * D, bfat + l * 384, Th, Sh, Hnh, N_NODES);

        init_kernel<<<INIT_BLOCKS, 256>>>();
        edge_logits   <<<EDGE_BLOCKS, 256>>>(ei);
        edge_aggregate<<<EDGE_BLOCKS, 256>>>(ei);

        gemm_f16<16, 2, false, true><<<GEMM_BLOCKS, 256, GEMM_SMEM_BYTES>>>(
            agg, Wop + (size_t)l * D * DV, bo, hnext, nullptr, nullptr, N_NODES);

        uint32_t* t = hcur; hcur = hnext; hnext = t;
    }

    out_kernel<<<(N_NODES + 31) / 32, 256>>>(hcur, Wout, bout, out);
}

// round 15
// speedup vs baseline: 1.1100x; 1.1100x over previous
#include <cuda_runtime.h>
#include <cuda_fp16.h>
#include <cstdint>

#define N_NODES 20000
#define N_EDGES 320000
#define E_TOT   (N_EDGES + N_NODES)   /* 340000, with self loops */
#define D_IN  32
#define D     128
#define DV    16
#define NV    8
#define D_OUT 8

#define LO_SCALE   2048.0f
#define LO_INV     4.8828125e-4f   /* 1/2048 */

// ---------------- scratch (static device memory; no allocs allowed) ----------
// activations packed per element: uint32 = {fp16 hi (low 16), fp16 lo*2048 (high 16)}
__device__ uint32_t g_hS0[N_NODES * D];
__device__ uint32_t g_hS1[N_NODES * D];
__device__ __half   g_Th [N_NODES * D];
__device__ __half   g_Sh [N_NODES * D];
__device__ __half   g_Hnh[N_NODES * D];
__device__ __half   g_lgh[E_TOT * NV];      // per-edge per-head logits (fp16)
__device__ float    g_s  [N_NODES * NV];
__device__ float    g_agg[N_NODES * DV];
__device__ int      g_is64;
// packed weights, TRANSPOSED to [n][k] so B chunks are k-contiguous
__device__ uint32_t g_W1p [D * D_IN];       // [128][32]
__device__ uint32_t g_W2p [D * D];          // [128][128]
__device__ uint32_t g_Wfat[2][384 * D];     // [Wt|Ws|Wh rows][128]
__device__ uint32_t g_Wop [2][D * DV];      // [128][16]
__device__ float    g_bfat[2][384];

// ---------------- dtype detection for edge_index ----------------------------
__global__ void detect_kernel(const int* __restrict__ idx) {
    int tid = threadIdx.x;
    int z = (idx[2 * tid + 1] == 0) ? 1 : 0;
    int all = __syncthreads_and(z);
    if (tid == 0) g_is64 = all;
}

__device__ __forceinline__ void load_edge(const void* __restrict__ idx, int e,
                                          int& s, int& d) {
    if (e >= N_EDGES) { s = d = e - N_EDGES; return; }  // self loop
    if (g_is64) {
        const long long* p = (const long long*)idx;
        s = (int)p[e];
        d = (int)p[N_EDGES + e];
    } else {
        const int* p = (const int*)idx;
        s = p[e];
        d = p[N_EDGES + e];
    }
}

// ---------------- fp16 hi/lo split helpers -----------------------------------
// lo plane scaled by 2^11 so it stays in the fp16 NORMAL range.
__device__ __forceinline__ uint32_t packhl(float v) {
    __half h = __float2half_rn(v);
    __half l = __float2half_rn((v - __half2float(h)) * LO_SCALE);
    return (uint32_t)__half_as_ushort(h) | ((uint32_t)__half_as_ushort(l) << 16);
}

#define MMA_F16(d, a, b)                                                      \
    asm volatile("mma.sync.aligned.m16n8k16.row.col.f32.f16.f16.f32 "         \
                 "{%0,%1,%2,%3}, {%4,%5,%6,%7}, {%8,%9}, {%0,%1,%2,%3};"      \
                 : "+f"(d[0]), "+f"(d[1]), "+f"(d[2]), "+f"(d[3])             \
                 : "r"(a[0]), "r"(a[1]), "r"(a[2]), "r"(a[3]),                \
                   "r"(b[0]), "r"(b[1]))

__device__ __forceinline__ void cp16(uint32_t smem_addr, const void* gptr, int src_bytes) {
    asm volatile("cp.async.cg.shared.global [%0], [%1], 16, %2;"
                 :: "r"(smem_addr), "l"(gptr), "r"(src_bytes));
}
#define CP_COMMIT() asm volatile("cp.async.commit_group;" ::: "memory")
#define CP_WAIT1()  asm volatile("cp.async.wait_group 1;" ::: "memory")
#define CP_WAIT0()  asm volatile("cp.async.wait_group 0;" ::: "memory")

#define GEMM_SA 24
#define GEMM_SB 24
#define GEMM_SMEM_WORDS (3 * 64 * GEMM_SA + 3 * 128 * GEMM_SB)
#define GEMM_SMEM_BYTES (GEMM_SMEM_WORDS * 4)   /* 55296 */

// ---------------- fp16-split tensor GEMM, 3-stage cp.async -------------------
// C[M, 128 per y-block] = relu(A[M,K] @ W[K,N] + b).
// smem keeps PACKED {hi,lo} words; fragments = LDS.64 + 2x byte_perm in loop.
// 3-stage ring: tile i lives in buffer i%3. prefetch(t+2) targets buffer
// (t-1)%3 whose readers all passed the end-of-(t-1) barrier -> ONE barrier
// per tile, no race. wait_group 1 at iter t drains through tile t+1.
// BM=64, BN=128, BK=16; 8 warps, warp tile 16x64; dual accumulator epilogue.
template <int K, int MODE, bool FAT, bool AF32>
__global__ __launch_bounds__(256, 2) void
gemm_f16(const void* __restrict__ Av, const uint32_t* __restrict__ Wp,
         const float* __restrict__ bias,
         void* __restrict__ out0, void* __restrict__ out1, void* __restrict__ out2,
         int M) {
    constexpr int BK = 16;
    constexpr int T  = K / BK;

    extern __shared__ __align__(16) uint32_t smem_raw[];
    typedef uint32_t ABuf[64][GEMM_SA];
    typedef uint32_t BBuf[128][GEMM_SB];
    ABuf* As = reinterpret_cast<ABuf*>(smem_raw);                        // [3]
    BBuf* Bs = reinterpret_cast<BBuf*>(smem_raw + 3 * 64 * GEMM_SA);     // [3]

    const int tid  = threadIdx.x;
    const int lane = tid & 31;
    const int wid  = tid >> 5;
    const int wm   = wid & 3;    // rows wm*16 .. +15
    const int wn   = wid >> 2;   // cols wn*64 .. +63
    const int m0   = blockIdx.x * 64;
    const int y    = FAT ? blockIdx.y : 0;

    const uint32_t* Wy = Wp + (size_t)y * 128 * K;
    const float*    by = bias + y * 128;

    float acc[8][4], accL[8][4];
#pragma unroll
    for (int nt = 0; nt < 8; nt++)
#pragma unroll
        for (int j = 0; j < 4; j++) { acc[nt][j] = 0.f; accL[nt][j] = 0.f; }

    const int arow = tid >> 2;          // 0..63
    const int ak4  = (tid & 3) * 4;     // 0,4,8,12

    auto prefetch = [&](int t, int buf) {
        if (!AF32) {
            const uint32_t* Ap = (const uint32_t*)Av;
            uint32_t dst = (uint32_t)__cvta_generic_to_shared(&As[buf][arow][ak4]);
            cp16(dst, &Ap[(size_t)(m0 + arow) * K + t * BK + ak4],
                 (m0 + arow < M) ? 16 : 0);
        }
#pragma unroll
        for (int i = 0; i < 2; i++) {
            int idx = tid + i * 256;
            int n   = idx >> 2;          // 0..127
            int k4  = (idx & 3) * 4;
            uint32_t dst = (uint32_t)__cvta_generic_to_shared(&Bs[buf][n][k4]);
            cp16(dst, &Wy[(size_t)n * K + t * BK + k4], 16);
        }
    };

    auto stageA_f32 = [&](int t, int buf) {   // AF32 path: ldg + split + STS
        const float* Af = (const float*)Av;
        float4 aF = make_float4(0.f, 0.f, 0.f, 0.f);
        if (m0 + arow < M)
            aF = *reinterpret_cast<const float4*>(&Af[(size_t)(m0 + arow) * K + t * BK + ak4]);
        As[buf][arow][ak4 + 0] = packhl(aF.x);
        As[buf][arow][ak4 + 1] = packhl(aF.y);
        As[buf][arow][ak4 + 2] = packhl(aF.z);
        As[buf][arow][ak4 + 3] = packhl(aF.w);
    };

    auto computeTile = [&](int buf) {
        const int r  = lane >> 2;   // 0..7
        const int c2 = (lane & 3) * 2;
        const int mb = wm * 16 + r;

        uint2 a0 = *reinterpret_cast<const uint2*>(&As[buf][mb][c2]);
        uint2 a1 = *reinterpret_cast<const uint2*>(&As[buf][mb + 8][c2]);
        uint2 a2 = *reinterpret_cast<const uint2*>(&As[buf][mb][c2 + 8]);
        uint2 a3 = *reinterpret_cast<const uint2*>(&As[buf][mb + 8][c2 + 8]);
        uint32_t ah[4], al[4];
        ah[0] = __byte_perm(a0.x, a0.y, 0x5410); al[0] = __byte_perm(a0.x, a0.y, 0x7632);
        ah[1] = __byte_perm(a1.x, a1.y, 0x5410); al[1] = __byte_perm(a1.x, a1.y, 0x7632);
        ah[2] = __byte_perm(a2.x, a2.y, 0x5410); al[2] = __byte_perm(a2.x, a2.y, 0x7632);
        ah[3] = __byte_perm(a3.x, a3.y, 0x5410); al[3] = __byte_perm(a3.x, a3.y, 0x7632);

#pragma unroll
        for (int nt = 0; nt < 8; nt++) {
            int nb = wn * 64 + nt * 8 + r;
            uint2 b0 = *reinterpret_cast<const uint2*>(&Bs[buf][nb][c2]);
            uint2 b1 = *reinterpret_cast<const uint2*>(&Bs[buf][nb][c2 + 8]);
            uint32_t bh[2], bl[2];
            bh[0] = __byte_perm(b0.x, b0.y, 0x5410); bl[0] = __byte_perm(b0.x, b0.y, 0x7632);
            bh[1] = __byte_perm(b1.x, b1.y, 0x5410); bl[1] = __byte_perm(b1.x, b1.y, 0x7632);
            MMA_F16(acc[nt],  ah, bh);
            MMA_F16(accL[nt], al, bh);
            MMA_F16(accL[nt], ah, bl);
        }
    };

    if (AF32) {
        // small-K path, non-pipelined (T <= 2)
#pragma unroll
        for (int t = 0; t < T; t++) {
            stageA_f32(t, 0);
            prefetch(t, 0);         // B only (AF32 skips A in prefetch)
            CP_COMMIT();
            CP_WAIT0();
            __syncthreads();
            computeTile(0);
            __syncthreads();
        }
    } else {
        prefetch(0, 0); CP_COMMIT();
        if (T > 1) { prefetch(1, 1); }
        CP_COMMIT();
        CP_WAIT1();
        __syncthreads();
#pragma unroll
        for (int t = 0; t < T; t++) {
            if (t + 2 < T) prefetch(t + 2, (t + 2) % 3);
            CP_COMMIT();
            computeTile(t % 3);
            CP_WAIT1();
            __syncthreads();
        }
    }

    // ---- epilogue (relu always): c0,c1 -> (row, col..col+1), c2,c3 -> row+8
    const int r   = lane >> 2;
    const int c2  = (lane & 3) * 2;
    const int row = m0 + wm * 16 + r;

    const int mode = FAT ? 1 : MODE;
    void* outp = FAT ? (y == 0 ? out0 : (y == 1 ? out1 : out2)) : out0;

#pragma unroll
    for (int nt = 0; nt < 8; nt++) {
        int col = wn * 64 + nt * 8 + c2;
        float b0 = by[col], b1 = by[col + 1];
        float v0 = fmaxf(acc[nt][0] + accL[nt][0] * LO_INV + b0, 0.f);
        float v1 = fmaxf(acc[nt][1] + accL[nt][1] * LO_INV + b1, 0.f);
        float v2 = fmaxf(acc[nt][2] + accL[nt][2] * LO_INV + b0, 0.f);
        float v3 = fmaxf(acc[nt][3] + accL[nt][3] * LO_INV + b1, 0.f);
        if (mode == 0) {
            float* C = (float*)outp;
            if (row < M)
                *reinterpret_cast<float2*>(&C[(size_t)row * 128 + col]) = make_float2(v0, v1);
            if (row + 8 < M)
                *reinterpret_cast<float2*>(&C[(size_t)(row + 8) * 128 + col]) = make_float2(v2, v3);
        } else if (mode == 1) {
            __half2* C = (__half2*)outp;
            if (row < M)     C[(size_t)row * 64 + (col >> 1)]       = __floats2half2_rn(v0, v1);
            if (row + 8 < M) C[(size_t)(row + 8) * 64 + (col >> 1)] = __floats2half2_rn(v2, v3);
        } else {
            uint32_t* C = (uint32_t*)outp;
            if (row < M)
                *reinterpret_cast<uint2*>(&C[(size_t)row * 128 + col]) =
                    make_uint2(packhl(v0), packhl(v1));
            if (row + 8 < M)
                *reinterpret_cast<uint2*>(&C[(size_t)(row + 8) * 128 + col]) =
                    make_uint2(packhl(v2), packhl(v3));
        }
    }
}

// ---------------- weight/bias packing (once per launch; cheap) ---------------
// Weights are packed AND transposed to [n][k].
__global__ void pack_all(const float* __restrict__ W1, const float* __restrict__ W2,
                         const float* __restrict__ Wt0, const float* __restrict__ Ws0,
                         const float* __restrict__ Wh0, const float* __restrict__ Wo0,
                         const float* __restrict__ bt0, const float* __restrict__ bs0,
                         const float* __restrict__ bh0,
                         const float* __restrict__ Wt1, const float* __restrict__ Ws1,
                         const float* __restrict__ Wh1, const float* __restrict__ Wo1,
                         const float* __restrict__ bt1, const float* __restrict__ bs1,
                         const float* __restrict__ bh1) {
    int i = blockIdx.x * blockDim.x + threadIdx.x;
    if (i < D_IN * D) {                       // W1 [32][128] -> [n*32 + k]
        int k = i >> 7, n = i & 127;
        g_W1p[n * D_IN + k] = packhl(W1[i]);
        return;
    }
    i -= D_IN * D;
    if (i < D * D) {                          // W2 [128][128] -> [n*128 + k]
        int k = i >> 7, n = i & 127;
        g_W2p[n * D + k] = packhl(W2[i]);
        return;
    }
    i -= D * D;
    if (i < 6 * D * D) {                      // fat: [which*128 + n][k]
        int m = i / (D * D), r = i % (D * D);
        int l = m / 3, which = m % 3;
        const float* src = (l == 0) ? (which == 0 ? Wt0 : which == 1 ? Ws0 : Wh0)
                                    : (which == 0 ? Wt1 : which == 1 ? Ws1 : Wh1);
        int k = r >> 7, c = r & 127;
        g_Wfat[l][(size_t)(which * 128 + c) * D + k] = packhl(src[r]);
        return;
    }
    i -= 6 * D * D;
    if (i < 2 * DV * D) {                     // Wo [16][128] -> [n*16 + k]
        int l = i / (DV * D), r = i % (DV * D);
        int k = r >> 7, n = r & 127;
        g_Wop[l][n * DV + k] = packhl((l == 0 ? Wo0 : Wo1)[r]);
        return;
    }
    i -= 2 * DV * D;
    if (i < 2 * 384) {
        int l = i / 384, r = i % 384;
        const float* b = (l == 0) ? (r < 128 ? bt0 : r < 256 ? bs0 : bh0)
                                  : (r < 128 ? bt1 : r < 256 ? bs1 : bh1);
        g_bfat[l][r] = b[r & 127];
    }
}
#define PACK_TOTAL (D_IN * D + D * D + 6 * D * D + 2 * DV * D + 2 * 384)

// ---------------- per-layer init: s = 0, agg = 0 -----------------------------
__global__ void init_kernel() {
    int i = blockIdx.x * blockDim.x + threadIdx.x;
    if (i < N_NODES * NV) g_s[i] = 0.f;
    if (i < N_NODES * DV) g_agg[i] = 0.f;
}

// ---------------- pass 1: logits + exp + segment sum (no max needed) ---------
// Logits tiny & >=0 (ReLU outputs of 0.02-scale projections): shift-free
// softmax is exact; fp16 stores perturb logits ~1e-7 absolute.
__global__ void edge_logits(const void* __restrict__ idx) {
    int gw   = (blockIdx.x * blockDim.x + threadIdx.x) >> 5;
    int lane = threadIdx.x & 31;
    int sub  = lane >> 4;
    int l    = lane & 15;
    int e    = gw * 2 + sub;
    bool ok  = (e < E_TOT);

    float v = 0.f;
    int s = 0, d = 0;
    if (ok) {
        load_edge(idx, e, s, d);
        uint4 tv = *reinterpret_cast<const uint4*>(&g_Th[(size_t)d * D + l * 8]);
        uint4 sv = *reinterpret_cast<const uint4*>(&g_Sh[(size_t)s * D + l * 8]);
        const __half2* tp = reinterpret_cast<const __half2*>(&tv);
        const __half2* sp = reinterpret_cast<const __half2*>(&sv);
#pragma unroll
        for (int j = 0; j < 4; j++) {
            float2 tf = __half22float2(tp[j]);
            float2 sf = __half22float2(sp[j]);
            v += tf.x * sf.x + tf.y * sf.y;
        }
    }
    v += __shfl_xor_sync(0xffffffffu, v, 1);
    if (ok && (l & 1) == 0) {
        int h = l >> 1;
        g_lgh[(size_t)e * NV + h] = __float2half(v);
        atomicAdd(&g_s[(size_t)d * NV + h], expf(v));
    }
}

// ---------------- pass 2: alpha-weighted head-mean message + segment sum -----
__global__ void edge_aggregate(const void* __restrict__ idx) {
    int gw   = (blockIdx.x * blockDim.x + threadIdx.x) >> 5;
    int lane = threadIdx.x & 31;
    int sub  = lane >> 4;
    int l    = lane & 15;
    int e    = gw * 2 + sub;
    bool ok  = (e < E_TOT);

    int s = 0, d = 0;
    if (ok) load_edge(idx, e, s, d);

    float a = 0.f;
    if (ok && l < 8) {
        float v = __half2float(g_lgh[(size_t)e * NV + l]);
        a = expf(v) / (g_s[(size_t)d * NV + l] + 1e-12f);
    }

    float acc = 0.f;
    int gbase = sub * 16;
#pragma unroll
    for (int h = 0; h < 8; h++) {
        float ah = __shfl_sync(0xffffffffu, a, gbase + h);
        if (ok) acc += __half2float(g_Hnh[(size_t)s * D + h * DV + l]) * ah;
    }
    if (ok) atomicAdd(&g_agg[(size_t)d * DV + l], acc * 0.125f);
}

// ---------------- output head: out[M,8] = (hi+lo/2048)[M,128] @ Wout + bout --
__global__ void out_kernel(const uint32_t* __restrict__ h, const float* __restrict__ W,
                           const float* __restrict__ b, float* __restrict__ out) {
    __shared__ float hs[32][132];
    __shared__ float Wsm[128][8];
    int tid = threadIdx.x;  // 256
    int m0  = blockIdx.x * 32;

#pragma unroll
    for (int i = 0; i < 4; i++) {
        int f = tid + i * 256;
        Wsm[f >> 3][f & 7] = W[f];
    }
#pragma unroll
    for (int i = 0; i < 4; i++) {
        int f4  = tid + i * 256;        // 1024 uint4 (4 packed elems each)
        int row = f4 >> 5;
        int c4  = (f4 & 31) * 4;
        uint4 v = make_uint4(0u, 0u, 0u, 0u);
        if (m0 + row < N_NODES)
            v = *reinterpret_cast<const uint4*>(&h[(size_t)(m0 + row) * 128 + c4]);
        uint32_t w[4] = {v.x, v.y, v.z, v.w};
#pragma unroll
        for (int j = 0; j < 4; j++) {
            __half2 p = *reinterpret_cast<__half2*>(&w[j]);
            hs[row][c4 + j] = __half2float(p.x) + __half2float(p.y) * LO_INV;
        }
    }
    __syncthreads();

    int row = tid >> 3, col = tid & 7;
    float acc = b[col];
#pragma unroll 8
    for (int k = 0; k < 128; k++) acc += hs[row][k] * Wsm[k][col];
    if (m0 + row < N_NODES) out[(size_t)(m0 + row) * 8 + col] = acc;
}

// ---------------- launch ------------------------------------------------------
extern "C" void kernel_launch(void* const* d_in, const int* in_sizes, int n_in,
                              void* d_out, int out_size) {
    const float* x    = (const float*)d_in[0];
    const void*  ei   = d_in[1];
    const float* W1   = (const float*)d_in[2];
    const float* b1   = (const float*)d_in[3];
    const float* W2   = (const float*)d_in[4];
    const float* b2   = (const float*)d_in[5];
    const float* Wout = (const float*)d_in[6];
    const float* bout = (const float*)d_in[7];
    float* out = (float*)d_out;

    uint32_t *hS0, *hS1, *W1p, *W2p, *Wfat, *Wop;
    __half *Th, *Sh, *Hnh;
    float *agg, *bfat;
    cudaGetSymbolAddress((void**)&hS0, g_hS0);
    cudaGetSymbolAddress((void**)&hS1, g_hS1);
    cudaGetSymbolAddress((void**)&Th, g_Th);
    cudaGetSymbolAddress((void**)&Sh, g_Sh);
    cudaGetSymbolAddress((void**)&Hnh, g_Hnh);
    cudaGetSymbolAddress((void**)&agg, g_agg);
    cudaGetSymbolAddress((void**)&W1p, g_W1p);
    cudaGetSymbolAddress((void**)&W2p, g_W2p);
    cudaGetSymbolAddress((void**)&Wfat, g_Wfat);
    cudaGetSymbolAddress((void**)&Wop, g_Wop);
    cudaGetSymbolAddress((void**)&bfat, g_bfat);

    // opt-in >48KB dynamic smem for the 3-stage ring
    cudaFuncSetAttribute(gemm_f16<32, 2, false, true>,
                         cudaFuncAttributeMaxDynamicSharedMemorySize, GEMM_SMEM_BYTES);
    cudaFuncSetAttribute(gemm_f16<128, 2, false, false>,
                         cudaFuncAttributeMaxDynamicSharedMemorySize, GEMM_SMEM_BYTES);
    cudaFuncSetAttribute(gemm_f16<128, 0, true, false>,
                         cudaFuncAttributeMaxDynamicSharedMemorySize, GEMM_SMEM_BYTES);
    cudaFuncSetAttribute(gemm_f16<16, 2, false, true>,
                         cudaFuncAttributeMaxDynamicSharedMemorySize, GEMM_SMEM_BYTES);

    const int GEMM_BLOCKS = (N_NODES + 63) / 64;        // 313
    const int EDGE_BLOCKS = (E_TOT * 16 + 255) / 256;   // 21250
    const int INIT_BLOCKS = (N_NODES * DV + 255) / 256; // 1250

    detect_kernel<<<1, 256>>>((const int*)ei);
    pack_all<<<(PACK_TOTAL + 255) / 256, 256>>>(
        W1, W2,
        (const float*)d_in[8],  (const float*)d_in[10], (const float*)d_in[12], (const float*)d_in[14],
        (const float*)d_in[9],  (const float*)d_in[11], (const float*)d_in[13],
        (const float*)d_in[16], (const float*)d_in[18], (const float*)d_in[20], (const float*)d_in[22],
        (const float*)d_in[17], (const float*)d_in[19], (const float*)d_in[21]);

    // embedding MLP (fp32 x in, packed activations out)
    gemm_f16<32, 2, false, true><<<GEMM_BLOCKS, 256, GEMM_SMEM_BYTES>>>(
        x, W1p, b1, hS0, nullptr, nullptr, N_NODES);
    gemm_f16<128, 2, false, false><<<GEMM_BLOCKS, 256, GEMM_SMEM_BYTES>>>(
        hS0, W2p, b2, hS1, nullptr, nullptr, N_NODES);

    uint32_t* hcur  = hS1;
    uint32_t* hnext = hS0;
    for (int l = 0; l < 2; l++) {
        const float* bo = (const float*)d_in[8 + l * 8 + 7];

        dim3 fatGrid(GEMM_BLOCKS, 3);
        gemm_f16<128, 0, true, false><<<fatGrid, 256, GEMM_SMEM_BYTES>>>(
            hcur, Wfat + (size_t)l * 384 * D, bfat + l * 384, Th, Sh, Hnh, N_NODES);

        init_kernel<<<INIT_BLOCKS, 256>>>();
        edge_logits   <<<EDGE_BLOCKS, 256>>>(ei);
        edge_aggregate<<<EDGE_BLOCKS, 256>>>(ei);

        gemm_f16<16, 2, false, true><<<GEMM_BLOCKS, 256, GEMM_SMEM_BYTES>>>(
            agg, Wop + (size_t)l * D * DV, bo, hnext, nullptr, nullptr, N_NODES);

        uint32_t* t = hcur; hcur = hnext; hnext = t;
    }

    out_kernel<<<(N_NODES + 31) / 32, 256>>>(hcur, Wout, bout, out);
}

// round 16
// speedup vs baseline: 1.1715x; 1.0554x over previous
#include <cuda_runtime.h>
#include <cuda_fp16.h>
#include <cstdint>

#define N_NODES 20000
#define N_EDGES 320000
#define E_TOT   (N_EDGES + N_NODES)   /* 340000, with self loops */
#define D_IN  32
#define D     128
#define DV    16
#define NV    8
#define D_OUT 8

#define LO_SCALE   2048.0f
#define LO_INV     4.8828125e-4f   /* 1/2048 */

// ---------------- scratch (static device memory; no allocs allowed) ----------
// activations packed per element: uint32 = {fp16 hi (low 16), fp16 lo*2048 (high 16)}
__device__ uint32_t g_hS0[N_NODES * D];
__device__ uint32_t g_hS1[N_NODES * D];
__device__ __half   g_Th [N_NODES * D];
__device__ __half   g_Sh [N_NODES * D];
__device__ __half   g_Hnh[N_NODES * D];
__device__ __half   g_lgh[E_TOT * NV];      // per-edge per-head logits (fp16)
__device__ float    g_s  [N_NODES * NV];
__device__ float    g_agg[N_NODES * DV];
__device__ int      g_is64;
// packed weights, TRANSPOSED to [n][k] so B chunks are k-contiguous
__device__ uint32_t g_W1p [D * D_IN];       // [128][32]
__device__ uint32_t g_W2p [D * D];          // [128][128]
__device__ uint32_t g_Wfat[2][384 * D];     // [Wt|Ws|Wh rows][128]
__device__ uint32_t g_Wop [2][D * DV];      // [128][16]
__device__ float    g_bfat[2][384];

// ---------------- dtype detection for edge_index ----------------------------
__global__ void detect_kernel(const int* __restrict__ idx) {
    int tid = threadIdx.x;
    int z = (idx[2 * tid + 1] == 0) ? 1 : 0;
    int all = __syncthreads_and(z);
    if (tid == 0) g_is64 = all;
}

__device__ __forceinline__ void load_edge(const void* __restrict__ idx, int e,
                                          int& s, int& d) {
    if (e >= N_EDGES) { s = d = e - N_EDGES; return; }  // self loop
    if (g_is64) {
        const long long* p = (const long long*)idx;
        s = (int)p[e];
        d = (int)p[N_EDGES + e];
    } else {
        const int* p = (const int*)idx;
        s = p[e];
        d = p[N_EDGES + e];
    }
}

// ---------------- fp16 hi/lo split helpers -----------------------------------
// lo plane scaled by 2^11 so it stays in the fp16 NORMAL range.
__device__ __forceinline__ uint32_t packhl(float v) {
    __half h = __float2half_rn(v);
    __half l = __float2half_rn((v - __half2float(h)) * LO_SCALE);
    return (uint32_t)__half_as_ushort(h) | ((uint32_t)__half_as_ushort(l) << 16);
}

#define MMA_F16(d, a, b)                                                      \
    asm volatile("mma.sync.aligned.m16n8k16.row.col.f32.f16.f16.f32 "         \
                 "{%0,%1,%2,%3}, {%4,%5,%6,%7}, {%8,%9}, {%0,%1,%2,%3};"      \
                 : "+f"(d[0]), "+f"(d[1]), "+f"(d[2]), "+f"(d[3])             \
                 : "r"(a[0]), "r"(a[1]), "r"(a[2]), "r"(a[3]),                \
                   "r"(b[0]), "r"(b[1]))

__device__ __forceinline__ void cp16(uint32_t smem_addr, const void* gptr, int src_bytes) {
    asm volatile("cp.async.cg.shared.global [%0], [%1], 16, %2;"
                 :: "r"(smem_addr), "l"(gptr), "r"(src_bytes));
}
#define CP_COMMIT() asm volatile("cp.async.commit_group;" ::: "memory")
#define CP_WAIT1()  asm volatile("cp.async.wait_group 1;" ::: "memory")
#define CP_WAIT0()  asm volatile("cp.async.wait_group 0;" ::: "memory")

#define GEMM_SA 24
#define GEMM_SB 24
#define GEMM_SMEM_WORDS (3 * 64 * GEMM_SA + 3 * 128 * GEMM_SB)
#define GEMM_SMEM_BYTES (GEMM_SMEM_WORDS * 4)   /* 55296 */

// ---------------- fp16-split tensor GEMM, 3-stage cp.async -------------------
// C[M, 128 per y-block] = relu(A[M,K] @ W[K,N] + b).
// smem keeps PACKED {hi,lo} words; fragments = LDS.64 + 2x byte_perm in loop.
// 3-stage ring, one barrier per tile (buffer t+2 = buffer (t-1)%3, already
// released by the end-of-(t-1) barrier).
// FAT y<2 (T,S): outputs are fp16 and feed only tiny softmax logits -> the
// lo-plane cross terms (~2^-11 rel) are below output quantization; run
// hi-plane-only (1 MMA/k-step). y==2 (Hn, linear path) keeps the full split.
template <int K, int MODE, bool FAT, bool AF32>
__global__ __launch_bounds__(256, 2) void
gemm_f16(const void* __restrict__ Av, const uint32_t* __restrict__ Wp,
         const float* __restrict__ bias,
         void* __restrict__ out0, void* __restrict__ out1, void* __restrict__ out2,
         int M) {
    constexpr int BK = 16;
    constexpr int T  = K / BK;

    extern __shared__ __align__(16) uint32_t smem_raw[];
    typedef uint32_t ABuf[64][GEMM_SA];
    typedef uint32_t BBuf[128][GEMM_SB];
    ABuf* As = reinterpret_cast<ABuf*>(smem_raw);                        // [3]
    BBuf* Bs = reinterpret_cast<BBuf*>(smem_raw + 3 * 64 * GEMM_SA);     // [3]

    const int tid  = threadIdx.x;
    const int lane = tid & 31;
    const int wid  = tid >> 5;
    const int wm   = wid & 3;    // rows wm*16 .. +15
    const int wn   = wid >> 2;   // cols wn*64 .. +63
    const int m0   = blockIdx.x * 64;
    const int y    = FAT ? blockIdx.y : 0;
    const bool fullSplit = !FAT || (y == 2);

    const uint32_t* Wy = Wp + (size_t)y * 128 * K;
    const float*    by = bias + y * 128;

    float acc[8][4], accL[8][4];
#pragma unroll
    for (int nt = 0; nt < 8; nt++)
#pragma unroll
        for (int j = 0; j < 4; j++) { acc[nt][j] = 0.f; accL[nt][j] = 0.f; }

    const int arow = tid >> 2;          // 0..63
    const int ak4  = (tid & 3) * 4;     // 0,4,8,12

    auto prefetch = [&](int t, int buf) {
        if (!AF32) {
            const uint32_t* Ap = (const uint32_t*)Av;
            uint32_t dst = (uint32_t)__cvta_generic_to_shared(&As[buf][arow][ak4]);
            cp16(dst, &Ap[(size_t)(m0 + arow) * K + t * BK + ak4],
                 (m0 + arow < M) ? 16 : 0);
        }
#pragma unroll
        for (int i = 0; i < 2; i++) {
            int idx = tid + i * 256;
            int n   = idx >> 2;          // 0..127
            int k4  = (idx & 3) * 4;
            uint32_t dst = (uint32_t)__cvta_generic_to_shared(&Bs[buf][n][k4]);
            cp16(dst, &Wy[(size_t)n * K + t * BK + k4], 16);
        }
    };

    auto stageA_f32 = [&](int t, int buf) {   // AF32 path: ldg + split + STS
        const float* Af = (const float*)Av;
        float4 aF = make_float4(0.f, 0.f, 0.f, 0.f);
        if (m0 + arow < M)
            aF = *reinterpret_cast<const float4*>(&Af[(size_t)(m0 + arow) * K + t * BK + ak4]);
        As[buf][arow][ak4 + 0] = packhl(aF.x);
        As[buf][arow][ak4 + 1] = packhl(aF.y);
        As[buf][arow][ak4 + 2] = packhl(aF.z);
        As[buf][arow][ak4 + 3] = packhl(aF.w);
    };

    auto computeTile = [&](int buf) {
        const int r  = lane >> 2;   // 0..7
        const int c2 = (lane & 3) * 2;
        const int mb = wm * 16 + r;

        uint2 a0 = *reinterpret_cast<const uint2*>(&As[buf][mb][c2]);
        uint2 a1 = *reinterpret_cast<const uint2*>(&As[buf][mb + 8][c2]);
        uint2 a2 = *reinterpret_cast<const uint2*>(&As[buf][mb][c2 + 8]);
        uint2 a3 = *reinterpret_cast<const uint2*>(&As[buf][mb + 8][c2 + 8]);
        uint32_t ah[4], al[4];
        ah[0] = __byte_perm(a0.x, a0.y, 0x5410); al[0] = __byte_perm(a0.x, a0.y, 0x7632);
        ah[1] = __byte_perm(a1.x, a1.y, 0x5410); al[1] = __byte_perm(a1.x, a1.y, 0x7632);
        ah[2] = __byte_perm(a2.x, a2.y, 0x5410); al[2] = __byte_perm(a2.x, a2.y, 0x7632);
        ah[3] = __byte_perm(a3.x, a3.y, 0x5410); al[3] = __byte_perm(a3.x, a3.y, 0x7632);

#pragma unroll
        for (int nt = 0; nt < 8; nt++) {
            int nb = wn * 64 + nt * 8 + r;
            uint2 b0 = *reinterpret_cast<const uint2*>(&Bs[buf][nb][c2]);
            uint2 b1 = *reinterpret_cast<const uint2*>(&Bs[buf][nb][c2 + 8]);
            uint32_t bh[2], bl[2];
            bh[0] = __byte_perm(b0.x, b0.y, 0x5410); bl[0] = __byte_perm(b0.x, b0.y, 0x7632);
            bh[1] = __byte_perm(b1.x, b1.y, 0x5410); bl[1] = __byte_perm(b1.x, b1.y, 0x7632);
            MMA_F16(acc[nt],  ah, bh);
            if (fullSplit) {
                MMA_F16(accL[nt], al, bh);
                MMA_F16(accL[nt], ah, bl);
            }
        }
    };

    if (AF32) {
        // small-K path, non-pipelined (T <= 2)
#pragma unroll
        for (int t = 0; t < T; t++) {
            stageA_f32(t, 0);
            prefetch(t, 0);         // B only (AF32 skips A in prefetch)
            CP_COMMIT();
            CP_WAIT0();
            __syncthreads();
            computeTile(0);
            __syncthreads();
        }
    } else {
        prefetch(0, 0); CP_COMMIT();
        if (T > 1) { prefetch(1, 1); }
        CP_COMMIT();
        CP_WAIT1();
        __syncthreads();
#pragma unroll
        for (int t = 0; t < T; t++) {
            if (t + 2 < T) prefetch(t + 2, (t + 2) % 3);
            CP_COMMIT();
            computeTile(t % 3);
            CP_WAIT1();
            __syncthreads();
        }
    }

    // ---- epilogue (relu always): c0,c1 -> (row, col..col+1), c2,c3 -> row+8
    const int r   = lane >> 2;
    const int c2  = (lane & 3) * 2;
    const int row = m0 + wm * 16 + r;

    const int mode = FAT ? 1 : MODE;
    void* outp = FAT ? (y == 0 ? out0 : (y == 1 ? out1 : out2)) : out0;

#pragma unroll
    for (int nt = 0; nt < 8; nt++) {
        int col = wn * 64 + nt * 8 + c2;
        float b0 = by[col], b1 = by[col + 1];
        float v0 = fmaxf(acc[nt][0] + accL[nt][0] * LO_INV + b0, 0.f);
        float v1 = fmaxf(acc[nt][1] + accL[nt][1] * LO_INV + b1, 0.f);
        float v2 = fmaxf(acc[nt][2] + accL[nt][2] * LO_INV + b0, 0.f);
        float v3 = fmaxf(acc[nt][3] + accL[nt][3] * LO_INV + b1, 0.f);
        if (mode == 0) {
            float* C = (float*)outp;
            if (row < M)
                *reinterpret_cast<float2*>(&C[(size_t)row * 128 + col]) = make_float2(v0, v1);
            if (row + 8 < M)
                *reinterpret_cast<float2*>(&C[(size_t)(row + 8) * 128 + col]) = make_float2(v2, v3);
        } else if (mode == 1) {
            __half2* C = (__half2*)outp;
            if (row < M)     C[(size_t)row * 64 + (col >> 1)]       = __floats2half2_rn(v0, v1);
            if (row + 8 < M) C[(size_t)(row + 8) * 64 + (col >> 1)] = __floats2half2_rn(v2, v3);
        } else {
            uint32_t* C = (uint32_t*)outp;
            if (row < M)
                *reinterpret_cast<uint2*>(&C[(size_t)row * 128 + col]) =
                    make_uint2(packhl(v0), packhl(v1));
            if (row + 8 < M)
                *reinterpret_cast<uint2*>(&C[(size_t)(row + 8) * 128 + col]) =
                    make_uint2(packhl(v2), packhl(v3));
        }
    }
}

// ---------------- weight/bias packing (once per launch; cheap) ---------------
// Weights are packed AND transposed to [n][k].
__global__ void pack_all(const float* __restrict__ W1, const float* __restrict__ W2,
                         const float* __restrict__ Wt0, const float* __restrict__ Ws0,
                         const float* __restrict__ Wh0, const float* __restrict__ Wo0,
                         const float* __restrict__ bt0, const float* __restrict__ bs0,
                         const float* __restrict__ bh0,
                         const float* __restrict__ Wt1, const float* __restrict__ Ws1,
                         const float* __restrict__ Wh1, const float* __restrict__ Wo1,
                         const float* __restrict__ bt1, const float* __restrict__ bs1,
                         const float* __restrict__ bh1) {
    int i = blockIdx.x * blockDim.x + threadIdx.x;
    if (i < D_IN * D) {                       // W1 [32][128] -> [n*32 + k]
        int k = i >> 7, n = i & 127;
        g_W1p[n * D_IN + k] = packhl(W1[i]);
        return;
    }
    i -= D_IN * D;
    if (i < D * D) {                          // W2 [128][128] -> [n*128 + k]
        int k = i >> 7, n = i & 127;
        g_W2p[n * D + k] = packhl(W2[i]);
        return;
    }
    i -= D * D;
    if (i < 6 * D * D) {                      // fat: [which*128 + n][k]
        int m = i / (D * D), r = i % (D * D);
        int l = m / 3, which = m % 3;
        const float* src = (l == 0) ? (which == 0 ? Wt0 : which == 1 ? Ws0 : Wh0)
                                    : (which == 0 ? Wt1 : which == 1 ? Ws1 : Wh1);
        int k = r >> 7, c = r & 127;
        g_Wfat[l][(size_t)(which * 128 + c) * D + k] = packhl(src[r]);
        return;
    }
    i -= 6 * D * D;
    if (i < 2 * DV * D) {                     // Wo [16][128] -> [n*16 + k]
        int l = i / (DV * D), r = i % (DV * D);
        int k = r >> 7, n = r & 127;
        g_Wop[l][n * DV + k] = packhl((l == 0 ? Wo0 : Wo1)[r]);
        return;
    }
    i -= 2 * DV * D;
    if (i < 2 * 384) {
        int l = i / 384, r = i % 384;
        const float* b = (l == 0) ? (r < 128 ? bt0 : r < 256 ? bs0 : bh0)
                                  : (r < 128 ? bt1 : r < 256 ? bs1 : bh1);
        g_bfat[l][r] = b[r & 127];
    }
}
#define PACK_TOTAL (D_IN * D + D * D + 6 * D * D + 2 * DV * D + 2 * 384)

// ---------------- per-layer init: s = 0, agg = 0 -----------------------------
__global__ void init_kernel() {
    int i = blockIdx.x * blockDim.x + threadIdx.x;
    if (i < N_NODES * NV) g_s[i] = 0.f;
    if (i < N_NODES * DV) g_agg[i] = 0.f;
}

// ---------------- pass 1: logits + exp + segment sum (no max needed) ---------
// 8 lanes per edge, lane = head: each lane owns head l's 16 contiguous dims
// (32 B of T + 32 B of S), computes the full head dot locally -> NO shuffles.
// 4 edges per warp. Logits tiny & >=0: shift-free softmax is exact.
__global__ void edge_logits(const void* __restrict__ idx) {
    int gw   = (blockIdx.x * blockDim.x + threadIdx.x) >> 5;
    int lane = threadIdx.x & 31;
    int sub  = lane >> 3;      // 0..3: edge within warp
    int l    = lane & 7;       // head
    int e    = gw * 4 + sub;
    bool ok  = (e < E_TOT);

    if (!ok) return;
    int s, d;
    load_edge(idx, e, s, d);

    const uint4* Tp = reinterpret_cast<const uint4*>(&g_Th[(size_t)d * D + l * 16]);
    const uint4* Sp = reinterpret_cast<const uint4*>(&g_Sh[(size_t)s * D + l * 16]);
    uint4 t0 = Tp[0], t1 = Tp[1];
    uint4 s0 = Sp[0], s1 = Sp[1];

    float v = 0.f;
    const __half2* tp0 = reinterpret_cast<const __half2*>(&t0);
    const __half2* tp1 = reinterpret_cast<const __half2*>(&t1);
    const __half2* sp0 = reinterpret_cast<const __half2*>(&s0);
    const __half2* sp1 = reinterpret_cast<const __half2*>(&s1);
#pragma unroll
    for (int j = 0; j < 4; j++) {
        float2 tf = __half22float2(tp0[j]);
        float2 sf = __half22float2(sp0[j]);
        v += tf.x * sf.x + tf.y * sf.y;
        float2 tg = __half22float2(tp1[j]);
        float2 sg = __half22float2(sp1[j]);
        v += tg.x * sg.x + tg.y * sg.y;
    }

    g_lgh[(size_t)e * NV + l] = __float2half(v);
    atomicAdd(&g_s[(size_t)d * NV + l], expf(v));
}

// ---------------- pass 2: alpha-weighted head-mean message + segment sum -----
__global__ void edge_aggregate(const void* __restrict__ idx) {
    int gw   = (blockIdx.x * blockDim.x + threadIdx.x) >> 5;
    int lane = threadIdx.x & 31;
    int sub  = lane >> 4;
    int l    = lane & 15;
    int e    = gw * 2 + sub;
    bool ok  = (e < E_TOT);

    int s = 0, d = 0;
    if (ok) load_edge(idx, e, s, d);

    float a = 0.f;
    if (ok && l < 8) {
        float v = __half2float(g_lgh[(size_t)e * NV + l]);
        a = expf(v) / (g_s[(size_t)d * NV + l] + 1e-12f);
    }

    float acc = 0.f;
    int gbase = sub * 16;
#pragma unroll
    for (int h = 0; h < 8; h++) {
        float ah = __shfl_sync(0xffffffffu, a, gbase + h);
        if (ok) acc += __half2float(g_Hnh[(size_t)s * D + h * DV + l]) * ah;
    }
    if (ok) atomicAdd(&g_agg[(size_t)d * DV + l], acc * 0.125f);
}

// ---------------- output head: out[M,8] = (hi+lo/2048)[M,128] @ Wout + bout --
__global__ void out_kernel(const uint32_t* __restrict__ h, const float* __restrict__ W,
                           const float* __restrict__ b, float* __restrict__ out) {
    __shared__ float hs[32][132];
    __shared__ float Wsm[128][8];
    int tid = threadIdx.x;  // 256
    int m0  = blockIdx.x * 32;

#pragma unroll
    for (int i = 0; i < 4; i++) {
        int f = tid + i * 256;
        Wsm[f >> 3][f & 7] = W[f];
    }
#pragma unroll
    for (int i = 0; i < 4; i++) {
        int f4  = tid + i * 256;        // 1024 uint4 (4 packed elems each)
        int row = f4 >> 5;
        int c4  = (f4 & 31) * 4;
        uint4 v = make_uint4(0u, 0u, 0u, 0u);
        if (m0 + row < N_NODES)
            v = *reinterpret_cast<const uint4*>(&h[(size_t)(m0 + row) * 128 + c4]);
        uint32_t w[4] = {v.x, v.y, v.z, v.w};
#pragma unroll
        for (int j = 0; j < 4; j++) {
            __half2 p = *reinterpret_cast<__half2*>(&w[j]);
            hs[row][c4 + j] = __half2float(p.x) + __half2float(p.y) * LO_INV;
        }
    }
    __syncthreads();

    int row = tid >> 3, col = tid & 7;
    float acc = b[col];
#pragma unroll 8
    for (int k = 0; k < 128; k++) acc += hs[row][k] * Wsm[k][col];
    if (m0 + row < N_NODES) out[(size_t)(m0 + row) * 8 + col] = acc;
}

// ---------------- launch ------------------------------------------------------
extern "C" void kernel_launch(void* const* d_in, const int* in_sizes, int n_in,
                              void* d_out, int out_size) {
    const float* x    = (const float*)d_in[0];
    const void*  ei   = d_in[1];
    const float* W1   = (const float*)d_in[2];
    const float* b1   = (const float*)d_in[3];
    const float* W2   = (const float*)d_in[4];
    const float* b2   = (const float*)d_in[5];
    const float* Wout = (const float*)d_in[6];
    const float* bout = (const float*)d_in[7];
    float* out = (float*)d_out;

    uint32_t *hS0, *hS1, *W1p, *W2p, *Wfat, *Wop;
    __half *Th, *Sh, *Hnh;
    float *agg, *bfat;
    cudaGetSymbolAddress((void**)&hS0, g_hS0);
    cudaGetSymbolAddress((void**)&hS1, g_hS1);
    cudaGetSymbolAddress((void**)&Th, g_Th);
    cudaGetSymbolAddress((void**)&Sh, g_Sh);
    cudaGetSymbolAddress((void**)&Hnh, g_Hnh);
    cudaGetSymbolAddress((void**)&agg, g_agg);
    cudaGetSymbolAddress((void**)&W1p, g_W1p);
    cudaGetSymbolAddress((void**)&W2p, g_W2p);
    cudaGetSymbolAddress((void**)&Wfat, g_Wfat);
    cudaGetSymbolAddress((void**)&Wop, g_Wop);
    cudaGetSymbolAddress((void**)&bfat, g_bfat);

    // opt-in >48KB dynamic smem for the 3-stage ring
    cudaFuncSetAttribute(gemm_f16<32, 2, false, true>,
                         cudaFuncAttributeMaxDynamicSharedMemorySize, GEMM_SMEM_BYTES);
    cudaFuncSetAttribute(gemm_f16<128, 2, false, false>,
                         cudaFuncAttributeMaxDynamicSharedMemorySize, GEMM_SMEM_BYTES);
    cudaFuncSetAttribute(gemm_f16<128, 0, true, false>,
                         cudaFuncAttributeMaxDynamicSharedMemorySize, GEMM_SMEM_BYTES);
    cudaFuncSetAttribute(gemm_f16<16, 2, false, true>,
                         cudaFuncAttributeMaxDynamicSharedMemorySize, GEMM_SMEM_BYTES);

    const int GEMM_BLOCKS = (N_NODES + 63) / 64;        // 313
    const int LOG_BLOCKS  = (E_TOT * 8 + 255) / 256;    // 10625
    const int AGG_BLOCKS  = (E_TOT * 16 + 255) / 256;   // 21250
    const int INIT_BLOCKS = (N_NODES * DV + 255) / 256; // 1250

    detect_kernel<<<1, 256>>>((const int*)ei);
    pack_all<<<(PACK_TOTAL + 255) / 256, 256>>>(
        W1, W2,
        (const float*)d_in[8],  (const float*)d_in[10], (const float*)d_in[12], (const float*)d_in[14],
        (const float*)d_in[9],  (const float*)d_in[11], (const float*)d_in[13],
        (const float*)d_in[16], (const float*)d_in[18], (const float*)d_in[20], (const float*)d_in[22],
        (const float*)d_in[17], (const float*)d_in[19], (const float*)d_in[21]);

    // embedding MLP (fp32 x in, packed activations out)
    gemm_f16<32, 2, false, true><<<GEMM_BLOCKS, 256, GEMM_SMEM_BYTES>>>(
        x, W1p, b1, hS0, nullptr, nullptr, N_NODES);
    gemm_f16<128, 2, false, false><<<GEMM_BLOCKS, 256, GEMM_SMEM_BYTES>>>(
        hS0, W2p, b2, hS1, nullptr, nullptr, N_NODES);

    uint32_t* hcur  = hS1;
    uint32_t* hnext = hS0;
    for (int l = 0; l < 2; l++) {
        const float* bo = (const float*)d_in[8 + l * 8 + 7];

        dim3 fatGrid(GEMM_BLOCKS, 3);
        gemm_f16<128, 0, true, false><<<fatGrid, 256, GEMM_SMEM_BYTES>>>(
            hcur, Wfat + (size_t)l * 384 * D, bfat + l * 384, Th, Sh, Hnh, N_NODES);

        init_kernel<<<INIT_BLOCKS, 256>>>();
        edge_logits   <<<LOG_BLOCKS, 256>>>(ei);
        edge_aggregate<<<AGG_BLOCKS, 256>>>(ei);

        gemm_f16<16, 2, false, true><<<GEMM_BLOCKS, 256, GEMM_SMEM_BYTES>>>(
            agg, Wop + (size_t)l * D * DV, bo, hnext, nullptr, nullptr, N_NODES);

        uint32_t* t = hcur; hcur = hnext; hnext = t;
    }

    out_kernel<<<(N_NODES + 31) / 32, 256>>>(hcur, Wout, bout, out);
}

// round 17
// speedup vs baseline: 1.1965x; 1.0213x over previous
#include <cuda_runtime.h>
#include <cuda_fp16.h>
#include <cstdint>

#define N_NODES 20000
#define N_EDGES 320000
#define E_TOT   (N_EDGES + N_NODES)   /* 340000, with self loops */
#define D_IN  32
#define D     128
#define DV    16
#define NV    8
#define D_OUT 8

#define LO_SCALE   2048.0f
#define LO_INV     4.8828125e-4f   /* 1/2048 */

// ---------------- scratch (static device memory; no allocs allowed) ----------
// activations packed per element: uint32 = {fp16 hi (low 16), fp16 lo*2048 (high 16)}
__device__ uint32_t g_hS0[N_NODES * D];
__device__ uint32_t g_hS1[N_NODES * D];
__device__ uint8_t  g_T8 [N_NODES * D];     // T projection, fp8 e5m2
__device__ uint8_t  g_S8 [N_NODES * D];     // S projection, fp8 e5m2
__device__ __half   g_Hnh[N_NODES * D];
__device__ __half   g_lgh[E_TOT * NV];      // per-edge per-head logits (fp16)
__device__ float    g_s  [N_NODES * NV];
__device__ float    g_agg[N_NODES * DV];
__device__ int      g_is64;
// packed weights, TRANSPOSED to [n][k] so B chunks are k-contiguous
__device__ uint32_t g_W1p [D * D_IN];       // [128][32]
__device__ uint32_t g_W2p [D * D];          // [128][128]
__device__ uint32_t g_Wfat[2][384 * D];     // [Wt|Ws|Wh rows][128]
__device__ uint32_t g_Wop [2][D * DV];      // [128][16]
__device__ float    g_bfat[2][384];

// ---------------- dtype detection for edge_index ----------------------------
__global__ void detect_kernel(const int* __restrict__ idx) {
    int tid = threadIdx.x;
    int z = (idx[2 * tid + 1] == 0) ? 1 : 0;
    int all = __syncthreads_and(z);
    if (tid == 0) g_is64 = all;
}

__device__ __forceinline__ void load_edge(const void* __restrict__ idx, int e,
                                          int& s, int& d) {
    if (e >= N_EDGES) { s = d = e - N_EDGES; return; }  // self loop
    if (g_is64) {
        const long long* p = (const long long*)idx;
        s = (int)p[e];
        d = (int)p[N_EDGES + e];
    } else {
        const int* p = (const int*)idx;
        s = p[e];
        d = p[N_EDGES + e];
    }
}

// ---------------- fp16 hi/lo split helpers -----------------------------------
// lo plane scaled by 2^11 so it stays in the fp16 NORMAL range.
__device__ __forceinline__ uint32_t packhl(float v) {
    __half h = __float2half_rn(v);
    __half l = __float2half_rn((v - __half2float(h)) * LO_SCALE);
    return (uint32_t)__half_as_ushort(h) | ((uint32_t)__half_as_ushort(l) << 16);
}

// ---------------- fp8 e5m2 helpers -------------------------------------------
// encode: two fp32 -> packed e5m2x2 (lo byte = first arg)
__device__ __forceinline__ uint16_t f2_e5m2(float lo, float hi) {
    uint16_t r;
    asm("cvt.rn.satfinite.e5m2x2.f32 %0, %1, %2;" : "=h"(r) : "f"(hi), "f"(lo));
    return r;
}
// decode: e5m2 is a bit-prefix of fp16 -> half = byte << 8 (byte_perm, no cvt)
__device__ __forceinline__ __half2 e5m2_lo_pair(uint32_t w) {   // bytes 0,1
    uint32_t r = __byte_perm(w, 0, 0x1404);
    return *reinterpret_cast<__half2*>(&r);
}
__device__ __forceinline__ __half2 e5m2_hi_pair(uint32_t w) {   // bytes 2,3
    uint32_t r = __byte_perm(w, 0, 0x3424);
    return *reinterpret_cast<__half2*>(&r);
}

#define MMA_F16(d, a, b)                                                      \
    asm volatile("mma.sync.aligned.m16n8k16.row.col.f32.f16.f16.f32 "         \
                 "{%0,%1,%2,%3}, {%4,%5,%6,%7}, {%8,%9}, {%0,%1,%2,%3};"      \
                 : "+f"(d[0]), "+f"(d[1]), "+f"(d[2]), "+f"(d[3])             \
                 : "r"(a[0]), "r"(a[1]), "r"(a[2]), "r"(a[3]),                \
                   "r"(b[0]), "r"(b[1]))

__device__ __forceinline__ void cp16(uint32_t smem_addr, const void* gptr, int src_bytes) {
    asm volatile("cp.async.cg.shared.global [%0], [%1], 16, %2;"
                 :: "r"(smem_addr), "l"(gptr), "r"(src_bytes));
}
#define CP_COMMIT() asm volatile("cp.async.commit_group;" ::: "memory")
#define CP_WAIT1()  asm volatile("cp.async.wait_group 1;" ::: "memory")
#define CP_WAIT0()  asm volatile("cp.async.wait_group 0;" ::: "memory")

#define GEMM_SA 24
#define GEMM_SB 24
#define GEMM_SMEM_WORDS (3 * 64 * GEMM_SA + 3 * 128 * GEMM_SB)
#define GEMM_SMEM_BYTES (GEMM_SMEM_WORDS * 4)   /* 55296 */

// ---------------- fp16-split tensor GEMM, 3-stage cp.async -------------------
// C[M, 128 per y-block] = relu(A[M,K] @ W[K,N] + b).
// 3-stage ring, one barrier per tile.
// MMA count by consumer precision (calibrated: storage quantization dominates):
//   FAT y<2 (T,S -> fp8 logits operands): hi-only, 1 MMA/k-step, fp8 out.
//   FAT y==2 (Hn -> fp16): 2 MMAs (drop al*bh, below fp16 storage noise).
//   non-FAT (packed 22-bit activations): full 3-MMA split.
template <int K, int MODE, bool FAT, bool AF32>
__global__ __launch_bounds__(256, 2) void
gemm_f16(const void* __restrict__ Av, const uint32_t* __restrict__ Wp,
         const float* __restrict__ bias,
         void* __restrict__ out0, void* __restrict__ out1, void* __restrict__ out2,
         int M) {
    constexpr int BK = 16;
    constexpr int T  = K / BK;

    extern __shared__ __align__(16) uint32_t smem_raw[];
    typedef uint32_t ABuf[64][GEMM_SA];
    typedef uint32_t BBuf[128][GEMM_SB];
    ABuf* As = reinterpret_cast<ABuf*>(smem_raw);                        // [3]
    BBuf* Bs = reinterpret_cast<BBuf*>(smem_raw + 3 * 64 * GEMM_SA);     // [3]

    const int tid  = threadIdx.x;
    const int lane = tid & 31;
    const int wid  = tid >> 5;
    const int wm   = wid & 3;    // rows wm*16 .. +15
    const int wn   = wid >> 2;   // cols wn*64 .. +63
    const int m0   = blockIdx.x * 64;
    const int y    = FAT ? blockIdx.y : 0;
    const int nm   = FAT ? (y == 2 ? 2 : 1) : 3;   // MMAs per k-step

    const uint32_t* Wy = Wp + (size_t)y * 128 * K;
    const float*    by = bias + y * 128;

    float acc[8][4], accL[8][4];
#pragma unroll
    for (int nt = 0; nt < 8; nt++)
#pragma unroll
        for (int j = 0; j < 4; j++) { acc[nt][j] = 0.f; accL[nt][j] = 0.f; }

    const int arow = tid >> 2;          // 0..63
    const int ak4  = (tid & 3) * 4;     // 0,4,8,12

    auto prefetch = [&](int t, int buf) {
        if (!AF32) {
            const uint32_t* Ap = (const uint32_t*)Av;
            uint32_t dst = (uint32_t)__cvta_generic_to_shared(&As[buf][arow][ak4]);
            cp16(dst, &Ap[(size_t)(m0 + arow) * K + t * BK + ak4],
                 (m0 + arow < M) ? 16 : 0);
        }
#pragma unroll
        for (int i = 0; i < 2; i++) {
            int idx = tid + i * 256;
            int n   = idx >> 2;          // 0..127
            int k4  = (idx & 3) * 4;
            uint32_t dst = (uint32_t)__cvta_generic_to_shared(&Bs[buf][n][k4]);
            cp16(dst, &Wy[(size_t)n * K + t * BK + k4], 16);
        }
    };

    auto stageA_f32 = [&](int t, int buf) {   // AF32 path: ldg + split + STS
        const float* Af = (const float*)Av;
        float4 aF = make_float4(0.f, 0.f, 0.f, 0.f);
        if (m0 + arow < M)
            aF = *reinterpret_cast<const float4*>(&Af[(size_t)(m0 + arow) * K + t * BK + ak4]);
        As[buf][arow][ak4 + 0] = packhl(aF.x);
        As[buf][arow][ak4 + 1] = packhl(aF.y);
        As[buf][arow][ak4 + 2] = packhl(aF.z);
        As[buf][arow][ak4 + 3] = packhl(aF.w);
    };

    auto computeTile = [&](int buf) {
        const int r  = lane >> 2;   // 0..7
        const int c2 = (lane & 3) * 2;
        const int mb = wm * 16 + r;

        uint2 a0 = *reinterpret_cast<const uint2*>(&As[buf][mb][c2]);
        uint2 a1 = *reinterpret_cast<const uint2*>(&As[buf][mb + 8][c2]);
        uint2 a2 = *reinterpret_cast<const uint2*>(&As[buf][mb][c2 + 8]);
        uint2 a3 = *reinterpret_cast<const uint2*>(&As[buf][mb + 8][c2 + 8]);
        uint32_t ah[4], al[4];
        ah[0] = __byte_perm(a0.x, a0.y, 0x5410);
        ah[1] = __byte_perm(a1.x, a1.y, 0x5410);
        ah[2] = __byte_perm(a2.x, a2.y, 0x5410);
        ah[3] = __byte_perm(a3.x, a3.y, 0x5410);
        if (nm == 3) {
            al[0] = __byte_perm(a0.x, a0.y, 0x7632);
            al[1] = __byte_perm(a1.x, a1.y, 0x7632);
            al[2] = __byte_perm(a2.x, a2.y, 0x7632);
            al[3] = __byte_perm(a3.x, a3.y, 0x7632);
        }

#pragma unroll
        for (int nt = 0; nt < 8; nt++) {
            int nb = wn * 64 + nt * 8 + r;
            uint2 b0 = *reinterpret_cast<const uint2*>(&Bs[buf][nb][c2]);
            uint2 b1 = *reinterpret_cast<const uint2*>(&Bs[buf][nb][c2 + 8]);
            uint32_t bh[2], bl[2];
            bh[0] = __byte_perm(b0.x, b0.y, 0x5410);
            bh[1] = __byte_perm(b1.x, b1.y, 0x5410);
            MMA_F16(acc[nt], ah, bh);
            if (nm >= 2) {
                bl[0] = __byte_perm(b0.x, b0.y, 0x7632);
                bl[1] = __byte_perm(b1.x, b1.y, 0x7632);
                MMA_F16(accL[nt], ah, bl);
            }
            if (nm == 3) {
                MMA_F16(accL[nt], al, bh);
            }
        }
    };

    if (AF32) {
        // small-K path, non-pipelined (T <= 2)
#pragma unroll
        for (int t = 0; t < T; t++) {
            stageA_f32(t, 0);
            prefetch(t, 0);         // B only (AF32 skips A in prefetch)
            CP_COMMIT();
            CP_WAIT0();
            __syncthreads();
            computeTile(0);
            __syncthreads();
        }
    } else {
        prefetch(0, 0); CP_COMMIT();
        if (T > 1) { prefetch(1, 1); }
        CP_COMMIT();
        CP_WAIT1();
        __syncthreads();
#pragma unroll
        for (int t = 0; t < T; t++) {
            if (t + 2 < T) prefetch(t + 2, (t + 2) % 3);
            CP_COMMIT();
            computeTile(t % 3);
            CP_WAIT1();
            __syncthreads();
        }
    }

    // ---- epilogue (relu always): c0,c1 -> (row, col..col+1), c2,c3 -> row+8
    const int r   = lane >> 2;
    const int c2  = (lane & 3) * 2;
    const int row = m0 + wm * 16 + r;

    // mode: 0 float, 1 half2, 2 packed-split, 3 fp8 e5m2
    const int mode = FAT ? (y == 2 ? 1 : 3) : MODE;
    void* outp = FAT ? (y == 0 ? out0 : (y == 1 ? out1 : out2)) : out0;

#pragma unroll
    for (int nt = 0; nt < 8; nt++) {
        int col = wn * 64 + nt * 8 + c2;
        float b0 = by[col], b1 = by[col + 1];
        float v0 = fmaxf(acc[nt][0] + accL[nt][0] * LO_INV + b0, 0.f);
        float v1 = fmaxf(acc[nt][1] + accL[nt][1] * LO_INV + b1, 0.f);
        float v2 = fmaxf(acc[nt][2] + accL[nt][2] * LO_INV + b0, 0.f);
        float v3 = fmaxf(acc[nt][3] + accL[nt][3] * LO_INV + b1, 0.f);
        if (mode == 0) {
            float* C = (float*)outp;
            if (row < M)
                *reinterpret_cast<float2*>(&C[(size_t)row * 128 + col]) = make_float2(v0, v1);
            if (row + 8 < M)
                *reinterpret_cast<float2*>(&C[(size_t)(row + 8) * 128 + col]) = make_float2(v2, v3);
        } else if (mode == 1) {
            __half2* C = (__half2*)outp;
            if (row < M)     C[(size_t)row * 64 + (col >> 1)]       = __floats2half2_rn(v0, v1);
            if (row + 8 < M) C[(size_t)(row + 8) * 64 + (col >> 1)] = __floats2half2_rn(v2, v3);
        } else if (mode == 3) {
            uint8_t* C = (uint8_t*)outp;
            if (row < M)
                *reinterpret_cast<uint16_t*>(&C[(size_t)row * 128 + col]) = f2_e5m2(v0, v1);
            if (row + 8 < M)
                *reinterpret_cast<uint16_t*>(&C[(size_t)(row + 8) * 128 + col]) = f2_e5m2(v2, v3);
        } else {
            uint32_t* C = (uint32_t*)outp;
            if (row < M)
                *reinterpret_cast<uint2*>(&C[(size_t)row * 128 + col]) =
                    make_uint2(packhl(v0), packhl(v1));
            if (row + 8 < M)
                *reinterpret_cast<uint2*>(&C[(size_t)(row + 8) * 128 + col]) =
                    make_uint2(packhl(v2), packhl(v3));
        }
    }
}

// ---------------- weight/bias packing (once per launch; cheap) ---------------
// Weights are packed AND transposed to [n][k].
__global__ void pack_all(const float* __restrict__ W1, const float* __restrict__ W2,
                         const float* __restrict__ Wt0, const float* __restrict__ Ws0,
                         const float* __restrict__ Wh0, const float* __restrict__ Wo0,
                         const float* __restrict__ bt0, const float* __restrict__ bs0,
                         const float* __restrict__ bh0,
                         const float* __restrict__ Wt1, const float* __restrict__ Ws1,
                         const float* __restrict__ Wh1, const float* __restrict__ Wo1,
                         const float* __restrict__ bt1, const float* __restrict__ bs1,
                         const float* __restrict__ bh1) {
    int i = blockIdx.x * blockDim.x + threadIdx.x;
    if (i < D_IN * D) {                       // W1 [32][128] -> [n*32 + k]
        int k = i >> 7, n = i & 127;
        g_W1p[n * D_IN + k] = packhl(W1[i]);
        return;
    }
    i -= D_IN * D;
    if (i < D * D) {                          // W2 [128][128] -> [n*128 + k]
        int k = i >> 7, n = i & 127;
        g_W2p[n * D + k] = packhl(W2[i]);
        return;
    }
    i -= D * D;
    if (i < 6 * D * D) {                      // fat: [which*128 + n][k]
        int m = i / (D * D), r = i % (D * D);
        int l = m / 3, which = m % 3;
        const float* src = (l == 0) ? (which == 0 ? Wt0 : which == 1 ? Ws0 : Wh0)
                                    : (which == 0 ? Wt1 : which == 1 ? Ws1 : Wh1);
        int k = r >> 7, c = r & 127;
        g_Wfat[l][(size_t)(which * 128 + c) * D + k] = packhl(src[r]);
        return;
    }
    i -= 6 * D * D;
    if (i < 2 * DV * D) {                     // Wo [16][128] -> [n*16 + k]
        int l = i / (DV * D), r = i % (DV * D);
        int k = r >> 7, n = r & 127;
        g_Wop[l][n * DV + k] = packhl((l == 0 ? Wo0 : Wo1)[r]);
        return;
    }
    i -= 2 * DV * D;
    if (i < 2 * 384) {
        int l = i / 384, r = i % 384;
        const float* b = (l == 0) ? (r < 128 ? bt0 : r < 256 ? bs0 : bh0)
                                  : (r < 128 ? bt1 : r < 256 ? bs1 : bh1);
        g_bfat[l][r] = b[r & 127];
    }
}
#define PACK_TOTAL (D_IN * D + D * D + 6 * D * D + 2 * DV * D + 2 * 384)

// ---------------- per-layer init: s = 0, agg = 0 -----------------------------
__global__ void init_kernel() {
    int i = blockIdx.x * blockDim.x + threadIdx.x;
    if (i < N_NODES * NV) g_s[i] = 0.f;
    if (i < N_NODES * DV) g_agg[i] = 0.f;
}

// ---------------- pass 1: logits + exp + segment sum (no max needed) ---------
// 8 lanes per edge, lane = head: lane owns head l's 16 dims (16 B of fp8 T +
// 16 B of fp8 S), full head dot computed locally -> no shuffles, 4 edges/warp.
// fp8 e5m2 T/S: logits are tiny (|e|~3e-4) so ~5% element error -> ~7e-6
// absolute logit error -> alpha error negligible. e5m2 decode = byte_perm.
__global__ void edge_logits(const void* __restrict__ idx) {
    int gw   = (blockIdx.x * blockDim.x + threadIdx.x) >> 5;
    int lane = threadIdx.x & 31;
    int sub  = lane >> 3;      // 0..3: edge within warp
    int l    = lane & 7;       // head
    int e    = gw * 4 + sub;
    if (e >= E_TOT) return;

    int s, d;
    load_edge(idx, e, s, d);

    uint4 t = *reinterpret_cast<const uint4*>(&g_T8[(size_t)d * D + l * 16]);
    uint4 sv = *reinterpret_cast<const uint4*>(&g_S8[(size_t)s * D + l * 16]);
    const uint32_t* tw = reinterpret_cast<const uint32_t*>(&t);
    const uint32_t* sw = reinterpret_cast<const uint32_t*>(&sv);

    float v = 0.f;
#pragma unroll
    for (int j = 0; j < 4; j++) {
        float2 ta = __half22float2(e5m2_lo_pair(tw[j]));
        float2 tb = __half22float2(e5m2_hi_pair(tw[j]));
        float2 sa = __half22float2(e5m2_lo_pair(sw[j]));
        float2 sb = __half22float2(e5m2_hi_pair(sw[j]));
        v += ta.x * sa.x + ta.y * sa.y + tb.x * sb.x + tb.y * sb.y;
    }

    g_lgh[(size_t)e * NV + l] = __float2half(v);
    atomicAdd(&g_s[(size_t)d * NV + l], expf(v));
}

// ---------------- pass 2: alpha-weighted head-mean message + segment sum -----
__global__ void edge_aggregate(const void* __restrict__ idx) {
    int gw   = (blockIdx.x * blockDim.x + threadIdx.x) >> 5;
    int lane = threadIdx.x & 31;
    int sub  = lane >> 4;
    int l    = lane & 15;
    int e    = gw * 2 + sub;
    bool ok  = (e < E_TOT);

    int s = 0, d = 0;
    if (ok) load_edge(idx, e, s, d);

    float a = 0.f;
    if (ok && l < 8) {
        float v = __half2float(g_lgh[(size_t)e * NV + l]);
        a = expf(v) / (g_s[(size_t)d * NV + l] + 1e-12f);
    }

    float acc = 0.f;
    int gbase = sub * 16;
#pragma unroll
    for (int h = 0; h < 8; h++) {
        float ah = __shfl_sync(0xffffffffu, a, gbase + h);
        if (ok) acc += __half2float(g_Hnh[(size_t)s * D + h * DV + l]) * ah;
    }
    if (ok) atomicAdd(&g_agg[(size_t)d * DV + l], acc * 0.125f);
}

// ---------------- output head: out[M,8] = (hi+lo/2048)[M,128] @ Wout + bout --
__global__ void out_kernel(const uint32_t* __restrict__ h, const float* __restrict__ W,
                           const float* __restrict__ b, float* __restrict__ out) {
    __shared__ float hs[32][132];
    __shared__ float Wsm[128][8];
    int tid = threadIdx.x;  // 256
    int m0  = blockIdx.x * 32;

#pragma unroll
    for (int i = 0; i < 4; i++) {
        int f = tid + i * 256;
        Wsm[f >> 3][f & 7] = W[f];
    }
#pragma unroll
    for (int i = 0; i < 4; i++) {
        int f4  = tid + i * 256;        // 1024 uint4 (4 packed elems each)
        int row = f4 >> 5;
        int c4  = (f4 & 31) * 4;
        uint4 v = make_uint4(0u, 0u, 0u, 0u);
        if (m0 + row < N_NODES)
            v = *reinterpret_cast<const uint4*>(&h[(size_t)(m0 + row) * 128 + c4]);
        uint32_t w[4] = {v.x, v.y, v.z, v.w};
#pragma unroll
        for (int j = 0; j < 4; j++) {
            __half2 p = *reinterpret_cast<__half2*>(&w[j]);
            hs[row][c4 + j] = __half2float(p.x) + __half2float(p.y) * LO_INV;
        }
    }
    __syncthreads();

    int row = tid >> 3, col = tid & 7;
    float acc = b[col];
#pragma unroll 8
    for (int k = 0; k < 128; k++) acc += hs[row][k] * Wsm[k][col];
    if (m0 + row < N_NODES) out[(size_t)(m0 + row) * 8 + col] = acc;
}

// ---------------- launch ------------------------------------------------------
extern "C" void kernel_launch(void* const* d_in, const int* in_sizes, int n_in,
                              void* d_out, int out_size) {
    const float* x    = (const float*)d_in[0];
    const void*  ei   = d_in[1];
    const float* W1   = (const float*)d_in[2];
    const float* b1   = (const float*)d_in[3];
    const float* W2   = (const float*)d_in[4];
    const float* b2   = (const float*)d_in[5];
    const float* Wout = (const float*)d_in[6];
    const float* bout = (const float*)d_in[7];
    float* out = (float*)d_out;

    uint32_t *hS0, *hS1, *W1p, *W2p, *Wfat, *Wop;
    uint8_t *T8, *S8;
    __half *Hnh;
    float *agg, *bfat;
    cudaGetSymbolAddress((void**)&hS0, g_hS0);
    cudaGetSymbolAddress((void**)&hS1, g_hS1);
    cudaGetSymbolAddress((void**)&T8, g_T8);
    cudaGetSymbolAddress((void**)&S8, g_S8);
    cudaGetSymbolAddress((void**)&Hnh, g_Hnh);
    cudaGetSymbolAddress((void**)&agg, g_agg);
    cudaGetSymbolAddress((void**)&W1p, g_W1p);
    cudaGetSymbolAddress((void**)&W2p, g_W2p);
    cudaGetSymbolAddress((void**)&Wfat, g_Wfat);
    cudaGetSymbolAddress((void**)&Wop, g_Wop);
    cudaGetSymbolAddress((void**)&bfat, g_bfat);

    // opt-in >48KB dynamic smem for the 3-stage ring
    cudaFuncSetAttribute(gemm_f16<32, 2, false, true>,
                         cudaFuncAttributeMaxDynamicSharedMemorySize, GEMM_SMEM_BYTES);
    cudaFuncSetAttribute(gemm_f16<128, 2, false, false>,
                         cudaFuncAttributeMaxDynamicSharedMemorySize, GEMM_SMEM_BYTES);
    cudaFuncSetAttribute(gemm_f16<128, 0, true, false>,
                         cudaFuncAttributeMaxDynamicSharedMemorySize, GEMM_SMEM_BYTES);
    cudaFuncSetAttribute(gemm_f16<16, 2, false, true>,
                         cudaFuncAttributeMaxDynamicSharedMemorySize, GEMM_SMEM_BYTES);

    const int GEMM_BLOCKS = (N_NODES + 63) / 64;        // 313
    const int LOG_BLOCKS  = (E_TOT * 8 + 255) / 256;    // 10625
    const int AGG_BLOCKS  = (E_TOT * 16 + 255) / 256;   // 21250
    const int INIT_BLOCKS = (N_NODES * DV + 255) / 256; // 1250

    detect_kernel<<<1, 256>>>((const int*)ei);
    pack_all<<<(PACK_TOTAL + 255) / 256, 256>>>(
        W1, W2,
        (const float*)d_in[8],  (const float*)d_in[10], (const float*)d_in[12], (const float*)d_in[14],
        (const float*)d_in[9],  (const float*)d_in[11], (const float*)d_in[13],
        (const float*)d_in[16], (const float*)d_in[18], (const float*)d_in[20], (const float*)d_in[22],
        (const float*)d_in[17], (const float*)d_in[19], (const float*)d_in[21]);

    // embedding MLP (fp32 x in, packed activations out)
    gemm_f16<32, 2, false, true><<<GEMM_BLOCKS, 256, GEMM_SMEM_BYTES>>>(
        x, W1p, b1, hS0, nullptr, nullptr, N_NODES);
    gemm_f16<128, 2, false, false><<<GEMM_BLOCKS, 256, GEMM_SMEM_BYTES>>>(
        hS0, W2p, b2, hS1, nullptr, nullptr, N_NODES);

    uint32_t* hcur  = hS1;
    uint32_t* hnext = hS0;
    for (int l = 0; l < 2; l++) {
        const float* bo = (const float*)d_in[8 + l * 8 + 7];

        dim3 fatGrid(GEMM_BLOCKS, 3);
        gemm_f16<128, 0, true, false><<<fatGrid, 256, GEMM_SMEM_BYTES>>>(
            hcur, Wfat + (size_t)l * 384 * D, bfat + l * 384, T8, S8, Hnh, N_NODES);

        init_kernel<<<INIT_BLOCKS, 256>>>();
        edge_logits   <<<LOG_BLOCKS, 256>>>(ei);
        edge_aggregate<<<AGG_BLOCKS, 256>>>(ei);

        gemm_f16<16, 2, false, true><<<GEMM_BLOCKS, 256, GEMM_SMEM_BYTES>>>(
            agg, Wop + (size_t)l * D * DV, bo, hnext, nullptr, nullptr, N_NODES);

        uint32_t* t = hcur; hcur = hnext; hnext = t;
    }

    out_kernel<<<(N_NODES + 31) / 32, 256>>>(hcur, Wout, bout, out);
}